// round 5
// baseline (speedup 1.0000x reference)
#include <cuda_runtime.h>
#include <cuda_bf16.h>
#include <math.h>

#define B_  32
#define T_  64
#define S_  128
#define E_  256
#define H_  512
#define ENC_ 512
#define V_  32000
#define G4_ (4*H_)   // 2048

// ---------------- scratch (static device globals; no allocation) ----------------
__device__ float g_emb [B_*T_*E_];          // [2048, 256]
__device__ float g_X   [B_*T_*G4_];         // [2048, 2048]  gates input proj + bias
__device__ float g_proj[B_*S_*H_];          // [32,128,512]  Wa @ enc
__device__ float g_bias[G4_];               // b_ih + b_hh
__device__ float g_h   [2][B_*H_];          // double-buffered hidden state
__device__ float g_c   [B_*H_];             // cell state
__device__ float g_hcat[B_*T_*(H_+ENC_)];   // [2048, 1024]  [h ; ctx] per (b,t)
__device__ float g_ho  [B_*T_*H_];          // [2048, 512]

// ---------------- init: state + combined bias ----------------
__global__ void k_init(const float* __restrict__ h0, const float* __restrict__ c0,
                       const float* __restrict__ b_ih, const float* __restrict__ b_hh) {
    int i = blockIdx.x * blockDim.x + threadIdx.x;
    if (i < B_*H_) { g_h[0][i] = h0[i]; g_c[i] = c0[i]; }
    if (i < G4_)   g_bias[i] = b_ih[i] + b_hh[i];
}

// ---------------- embedding gather: g_emb[bt] = table[tok[bt]] ----------------
__global__ void k_embed(const int* __restrict__ tok, const float* __restrict__ table) {
    int bt = blockIdx.x;             // 0..2047  (= b*T + t, matches gold row-major)
    int e  = threadIdx.x;            // 0..255
    g_emb[bt*E_ + e] = table[tok[bt]*E_ + e];
}

// ---------------- generic SGEMM: C[M,N] = A[M,K] @ Bw[N,K]^T + bias ----------------
// 128x128 tile, BK=16, 256 threads, 8x8 per thread. All dims exactly divisible.
__global__ void __launch_bounds__(256)
k_gemm(const float* __restrict__ A, const float* __restrict__ Bw,
       const float* __restrict__ bias, float* __restrict__ C,
       int M, int N, int K) {
    __shared__ float As[16][128];
    __shared__ float Bs[16][128];
    int tid = threadIdx.x;
    int bm = blockIdx.y * 128, bn = blockIdx.x * 128;
    int tm = (tid >> 4) * 8;     // 0..120
    int tn = (tid & 15) * 8;     // 0..120
    float acc[8][8];
    #pragma unroll
    for (int i = 0; i < 8; i++)
        #pragma unroll
        for (int j = 0; j < 8; j++) acc[i][j] = 0.f;

    for (int k0 = 0; k0 < K; k0 += 16) {
        // load A tile (128 rows x 16 cols), transposed into As[k][m]
        #pragma unroll
        for (int i = 0; i < 2; i++) {
            int f   = tid * 2 + i;           // 0..511 float4 index
            int row = f >> 2;                // 0..127
            int col = (f & 3) * 4;           // 0,4,8,12
            float4 v = *(const float4*)&A[(size_t)(bm + row) * K + k0 + col];
            As[col+0][row] = v.x; As[col+1][row] = v.y;
            As[col+2][row] = v.z; As[col+3][row] = v.w;
        }
        // load B tile (weight rows bn..bn+127, cols k0..k0+15) into Bs[k][n]
        #pragma unroll
        for (int i = 0; i < 2; i++) {
            int f   = tid * 2 + i;
            int row = f >> 2;
            int col = (f & 3) * 4;
            float4 v = *(const float4*)&Bw[(size_t)(bn + row) * K + k0 + col];
            Bs[col+0][row] = v.x; Bs[col+1][row] = v.y;
            Bs[col+2][row] = v.z; Bs[col+3][row] = v.w;
        }
        __syncthreads();
        #pragma unroll
        for (int k = 0; k < 16; k++) {
            float a[8], b[8];
            float4 a0 = *(const float4*)&As[k][tm];
            float4 a1 = *(const float4*)&As[k][tm+4];
            float4 b0 = *(const float4*)&Bs[k][tn];
            float4 b1 = *(const float4*)&Bs[k][tn+4];
            a[0]=a0.x; a[1]=a0.y; a[2]=a0.z; a[3]=a0.w;
            a[4]=a1.x; a[5]=a1.y; a[6]=a1.z; a[7]=a1.w;
            b[0]=b0.x; b[1]=b0.y; b[2]=b0.z; b[3]=b0.w;
            b[4]=b1.x; b[5]=b1.y; b[6]=b1.z; b[7]=b1.w;
            #pragma unroll
            for (int i = 0; i < 8; i++)
                #pragma unroll
                for (int j = 0; j < 8; j++)
                    acc[i][j] += a[i] * b[j];
        }
        __syncthreads();
    }
    #pragma unroll
    for (int i = 0; i < 8; i++) {
        #pragma unroll
        for (int j = 0; j < 8; j++) {
            float v = acc[i][j];
            if (bias) v += bias[bn + tn + j];
            C[(size_t)(bm + tm + i) * N + bn + tn + j] = v;
        }
    }
}

// ---------------- per-step gates + LSTM pointwise ----------------
// grid = 256 blocks; block handles u in {ub, ub+1}, all 32 batches, all 4 gates.
// 256 threads: r = tid/32 in [0,8) -> (q = r>>2 selects u, gate = r&3), b = tid%32.
__global__ void __launch_bounds__(256)
k_gates(int t, const float* __restrict__ W_hh) {
    __shared__ float h_sh[32][65];
    __shared__ float sg[8][33];
    const float* h_in  = g_h[t & 1];
    float*       h_out = g_h[(t + 1) & 1];
    int tid  = threadIdx.x;
    int r    = tid >> 5, b = tid & 31;
    int ub   = blockIdx.x * 2;
    int gate = r & 3, q = r >> 2;
    int row  = gate * H_ + ub + q;
    const float* Wrow = W_hh + (size_t)row * H_;

    float acc = 0.f;
    for (int kk = 0; kk < H_; kk += 64) {
        #pragma unroll
        for (int i = 0; i < 8; i++) {
            int idx = tid + i * 256;
            int bb = idx >> 6, k = idx & 63;
            h_sh[bb][k] = h_in[bb * H_ + kk + k];
        }
        __syncthreads();
        #pragma unroll
        for (int k = 0; k < 64; k++)
            acc += Wrow[kk + k] * h_sh[b][k];
        __syncthreads();
    }
    // add precomputed input projection (includes both biases)
    float gv = acc + g_X[(size_t)(b * T_ + t) * G4_ + row];
    sg[r][b] = gv;
    __syncthreads();

    if (tid < 64) {
        int q2 = tid >> 5, b2 = tid & 31;
        int u  = ub + q2;
        float iv = sg[q2*4 + 0][b2];
        float fv = sg[q2*4 + 1][b2];
        float gg = sg[q2*4 + 2][b2];
        float ov = sg[q2*4 + 3][b2];
        float si = 1.f / (1.f + expf(-iv));
        float sf = 1.f / (1.f + expf(-fv));
        float so = 1.f / (1.f + expf(-ov));
        float c_old = g_c[b2 * H_ + u];
        float c_new = sf * c_old + si * tanhf(gg);
        float h_new = so * tanhf(c_new);
        g_c[b2 * H_ + u]  = c_new;
        h_out[b2 * H_ + u] = h_new;
    }
}

// ---------------- per-step attention: scores -> masked softmax -> ctx ----------------
// grid = 32 blocks (one per batch), 256 threads.
__global__ void __launch_bounds__(256)
k_attn(int t, const float* __restrict__ enc, const int* __restrict__ lens) {
    int b = blockIdx.x;
    __shared__ float h_sh[H_];
    __shared__ float sc[S_];
    __shared__ float red[40];
    const float* h_cur = g_h[(t + 1) & 1] + b * H_;
    int tid = threadIdx.x;
    for (int i = tid; i < H_; i += 256) h_sh[i] = h_cur[i];
    __syncthreads();

    int warp = tid >> 5, lane = tid & 31;
    // scores[s] = h . proj_enc[b,s]
    for (int s = warp; s < S_; s += 8) {
        const float* pr = g_proj + ((size_t)b * S_ + s) * H_;
        float a = 0.f;
        for (int k = lane; k < H_; k += 32) a += h_sh[k] * pr[k];
        #pragma unroll
        for (int o = 16; o; o >>= 1) a += __shfl_xor_sync(0xFFFFFFFFu, a, o);
        if (lane == 0) sc[s] = a;
    }
    __syncthreads();
    int len = lens[b];
    if (tid < S_ && tid >= len) sc[tid] = -1e9f;
    __syncthreads();

    // max over 128 (threads 0..127 hold values; warps 4..7 contribute -inf/0)
    float m = (tid < S_) ? sc[tid] : -1e30f;
    #pragma unroll
    for (int o = 16; o; o >>= 1) m = fmaxf(m, __shfl_xor_sync(0xFFFFFFFFu, m, o));
    if (lane == 0) red[warp] = m;
    __syncthreads();
    if (tid == 0) {
        float mm = red[0];
        for (int i = 1; i < 8; i++) mm = fmaxf(mm, red[i]);
        red[32] = mm;
    }
    __syncthreads();
    float mx = red[32];

    float p = (tid < S_) ? expf(sc[tid] - mx) : 0.f;
    float ps = p;
    #pragma unroll
    for (int o = 16; o; o >>= 1) ps += __shfl_xor_sync(0xFFFFFFFFu, ps, o);
    if (lane == 0) red[warp] = ps;
    __syncthreads();
    if (tid == 0) {
        float sm = 0.f;
        for (int i = 0; i < 8; i++) sm += red[i];
        red[33] = 1.f / sm;
    }
    __syncthreads();
    if (tid < S_) sc[tid] = p * red[33];
    __syncthreads();

    // ctx[e] = sum_s att[s] * enc[b,s,e]; write [h ; ctx] row for (b,t)
    float* dst = g_hcat + (size_t)(b * T_ + t) * (H_ + ENC_);
    const float* eb = enc + (size_t)b * S_ * ENC_;
    for (int e = tid; e < ENC_; e += 256) {
        float a = 0.f;
        #pragma unroll 8
        for (int s = 0; s < S_; s++) a += sc[s] * eb[(size_t)s * ENC_ + e];
        dst[H_ + e] = a;
    }
    for (int i = tid; i < H_; i += 256) dst[i] = h_sh[i];
}

// ---------------- launch ----------------
extern "C" void kernel_launch(void* const* d_in, const int* in_sizes, int n_in,
                              void* d_out, int out_size) {
    const int*   gold   = (const int*)  d_in[0];
    const float* enc    = (const float*)d_in[1];
    const int*   lens   = (const int*)  d_in[2];
    const float* h0     = (const float*)d_in[3];
    const float* c0     = (const float*)d_in[4];
    const float* table  = (const float*)d_in[5];
    const float* W_ih   = (const float*)d_in[6];
    const float* W_hh   = (const float*)d_in[7];
    const float* b_ih   = (const float*)d_in[8];
    const float* b_hh   = (const float*)d_in[9];
    const float* Wa     = (const float*)d_in[10];
    const float* Wc_w   = (const float*)d_in[11];
    const float* Wc_b   = (const float*)d_in[12];
    const float* Wo_w   = (const float*)d_in[13];
    const float* Wo_b   = (const float*)d_in[14];
    float* out = (float*)d_out;

    // Symbol address lookups (host-side queries; not stream ops, capture-safe)
    float *p_emb, *p_X, *p_proj, *p_hcat, *p_ho, *p_bias;
    cudaGetSymbolAddress((void**)&p_emb,  g_emb);
    cudaGetSymbolAddress((void**)&p_X,    g_X);
    cudaGetSymbolAddress((void**)&p_proj, g_proj);
    cudaGetSymbolAddress((void**)&p_hcat, g_hcat);
    cudaGetSymbolAddress((void**)&p_ho,   g_ho);
    cudaGetSymbolAddress((void**)&p_bias, g_bias);

    // init state + combined bias
    k_init<<<64, 256>>>(h0, c0, b_ih, b_hh);
    // embedding gather
    k_embed<<<B_*T_, 256>>>(gold, table);
    // X = emb @ W_ih^T + (b_ih+b_hh)   [2048 x 2048, K=256]
    k_gemm<<<dim3(G4_/128, (B_*T_)/128), 256>>>(p_emb, W_ih, p_bias, p_X, B_*T_, G4_, E_);
    // proj_enc = enc @ Wa^T            [4096 x 512, K=512]
    k_gemm<<<dim3(H_/128, (B_*S_)/128), 256>>>(enc, Wa, nullptr, p_proj, B_*S_, H_, ENC_);

    // sequential decode loop
    for (int t = 0; t < T_; t++) {
        k_gates<<<256, 256>>>(t, W_hh);
        k_attn<<<32, 256>>>(t, enc, lens);
    }

    // HO = [h;ctx] @ Wc_w^T + Wc_b     [2048 x 512, K=1024]
    k_gemm<<<dim3(H_/128, (B_*T_)/128), 256>>>(p_hcat, Wc_w, Wc_b, p_ho, B_*T_, H_, H_+ENC_);
    // logits = HO @ Wo_w^T + Wo_b      [2048 x 32000, K=512] -> d_out
    k_gemm<<<dim3(V_/128, (B_*T_)/128), 256>>>(p_ho, Wo_w, Wo_b, out, B_*T_, V_, H_);
}

// round 8
// speedup vs baseline: 1.3170x; 1.3170x over previous
#include <cuda_runtime.h>
#include <cuda_bf16.h>
#include <math.h>
#include <stdint.h>

#define B_  32
#define T_  64
#define S_  128
#define E_  256
#define H_  512
#define ENC_ 512
#define V_  32000
#define G4_ (4*H_)   // 2048
#define BT_ (B_*T_)  // 2048
#define KBIG 1536    // 3 * H_ : [hoHi|hoHi|hoLo] x [WoHi|WoLo|WoHi]
#define NKIT 48      // KBIG / 32

// ---------------- scratch (static device globals; no allocation) ----------------
__device__ float g_emb [BT_*E_];
__device__ float g_X   [BT_*G4_];
__device__ float g_proj[B_*S_*H_];
__device__ float g_bias[G4_];
__device__ float g_h   [2][B_*H_];
__device__ float g_c   [B_*H_];
__device__ float g_hcat[BT_*(H_+ENC_)];
__device__ float g_ho  [BT_*H_];
// K-concatenated bf16 operands for the HMMA logits GEMM
__device__ __align__(128) __nv_bfloat16 g_Abig[BT_*KBIG];   // 6.3 MB
__device__ __align__(128) __nv_bfloat16 g_Bbig[(size_t)V_*KBIG]; // 98 MB

// ---------------- init: state + combined bias ----------------
__global__ void k_init(const float* __restrict__ h0, const float* __restrict__ c0,
                       const float* __restrict__ b_ih, const float* __restrict__ b_hh) {
    int i = blockIdx.x * blockDim.x + threadIdx.x;
    if (i < B_*H_) { g_h[0][i] = h0[i]; g_c[i] = c0[i]; }
    if (i < G4_)   g_bias[i] = b_ih[i] + b_hh[i];
}

// ---------------- embedding gather ----------------
__global__ void k_embed(const int* __restrict__ tok, const float* __restrict__ table) {
    int bt = blockIdx.x;
    int e  = threadIdx.x;
    g_emb[bt*E_ + e] = table[tok[bt]*E_ + e];
}

// ---------------- fp32 -> bf16 hi/lo splits into K-concat layouts ----------------
__global__ void k_splitA(const float* __restrict__ src) {   // ho [2048,512]
    int i = blockIdx.x * blockDim.x + threadIdx.x;
    if (i < BT_*H_) {
        int row = i >> 9, k = i & 511;
        float a = src[i];
        __nv_bfloat16 h = __float2bfloat16(a);
        __nv_bfloat16 l = __float2bfloat16(a - __bfloat162float(h));
        size_t b = (size_t)row * KBIG;
        g_Abig[b + k]        = h;   // span0: hoHi
        g_Abig[b + 512 + k]  = h;   // span1: hoHi
        g_Abig[b + 1024 + k] = l;   // span2: hoLo
    }
}
__global__ void k_splitB(const float* __restrict__ src) {   // Wo_w [32000,512]
    int i = blockIdx.x * blockDim.x + threadIdx.x;
    if (i < V_*H_) {
        int row = i >> 9, k = i & 511;
        float a = src[i];
        __nv_bfloat16 h = __float2bfloat16(a);
        __nv_bfloat16 l = __float2bfloat16(a - __bfloat162float(h));
        size_t b = (size_t)row * KBIG;
        g_Bbig[b + k]        = h;   // span0: WoHi
        g_Bbig[b + 512 + k]  = l;   // span1: WoLo
        g_Bbig[b + 1024 + k] = h;   // span2: WoHi
    }
}

// ---------------- mma.sync helpers ----------------
__device__ __forceinline__ void ldsm_x4(uint32_t addr, uint32_t* r) {
    asm volatile("ldmatrix.sync.aligned.m8n8.x4.shared.b16 {%0,%1,%2,%3}, [%4];"
        : "=r"(r[0]), "=r"(r[1]), "=r"(r[2]), "=r"(r[3]) : "r"(addr));
}
__device__ __forceinline__ void mma16816(float* d, const uint32_t* a, const uint32_t* b) {
    asm volatile("mma.sync.aligned.m16n8k16.row.col.f32.bf16.bf16.f32 "
        "{%0,%1,%2,%3}, {%4,%5,%6,%7}, {%8,%9}, {%0,%1,%2,%3};"
        : "+f"(d[0]), "+f"(d[1]), "+f"(d[2]), "+f"(d[3])
        : "r"(a[0]), "r"(a[1]), "r"(a[2]), "r"(a[3]), "r"(b[0]), "r"(b[1]));
}
__device__ __forceinline__ void cp16(uint32_t dst, const void* src) {
    asm volatile("cp.async.cg.shared.global [%0], [%1], 16;" :: "r"(dst), "l"(src));
}

// ---------------- HMMA logits GEMM ----------------
// C[2048, 32000] = A'[2048,1536] @ B'[32000,1536]^T + bias
// CTA 128x128, 8 warps (2m x 4n), warp 64x32, BK=32, double-buffered cp.async.
__global__ void __launch_bounds__(256)
k_hmma(const __nv_bfloat16* __restrict__ A, const __nv_bfloat16* __restrict__ Bw,
       const float* __restrict__ bias, float* __restrict__ C) {
    __shared__ __align__(128) __nv_bfloat16 sA[2][128*32];
    __shared__ __align__(128) __nv_bfloat16 sB[2][128*32];
    int tid = threadIdx.x, lane = tid & 31, warp = tid >> 5;
    int wm = warp >> 2, wn = warp & 3;          // warp grid 2 x 4
    int bm = blockIdx.y * 128, bn = blockIdx.x * 128;
    uint32_t sAb = (uint32_t)__cvta_generic_to_shared(sA);
    uint32_t sBb = (uint32_t)__cvta_generic_to_shared(sB);

    float acc[4][4][4];
    #pragma unroll
    for (int i = 0; i < 4; i++)
        #pragma unroll
        for (int j = 0; j < 4; j++)
            #pragma unroll
            for (int v = 0; v < 4; v++) acc[i][j][v] = 0.f;

    // per-thread cp.async chunks: 2 for A, 2 for B (16B each). chunk = row*4 + c
    int ch0 = tid * 2, ch1 = tid * 2 + 1;
    int r0 = ch0 >> 2, c0 = ch0 & 3;
    int r1 = ch1 >> 2, c1 = ch1 & 3;
    uint32_t dA0 = (uint32_t)(r0 * 64 + ((c0 ^ (r0 & 3)) << 4));
    uint32_t dA1 = (uint32_t)(r1 * 64 + ((c1 ^ (r1 & 3)) << 4));

    // prologue: stage 0
    {
        int k0 = 0;
        cp16(sAb + dA0, &A[(size_t)(bm + r0) * KBIG + k0 + c0 * 8]);
        cp16(sAb + dA1, &A[(size_t)(bm + r1) * KBIG + k0 + c1 * 8]);
        cp16(sBb + dA0, &Bw[(size_t)(bn + r0) * KBIG + k0 + c0 * 8]);
        cp16(sBb + dA1, &Bw[(size_t)(bn + r1) * KBIG + k0 + c1 * 8]);
        asm volatile("cp.async.commit_group;");
    }

    #pragma unroll 1
    for (int kt = 0; kt < NKIT; kt++) {
        if (kt + 1 < NKIT) {
            int k0 = (kt + 1) * 32;
            uint32_t so = ((kt + 1) & 1) ? 8192u : 0u;
            cp16(sAb + so + dA0, &A[(size_t)(bm + r0) * KBIG + k0 + c0 * 8]);
            cp16(sAb + so + dA1, &A[(size_t)(bm + r1) * KBIG + k0 + c1 * 8]);
            cp16(sBb + so + dA0, &Bw[(size_t)(bn + r0) * KBIG + k0 + c0 * 8]);
            cp16(sBb + so + dA1, &Bw[(size_t)(bn + r1) * KBIG + k0 + c1 * 8]);
            asm volatile("cp.async.commit_group;");
            asm volatile("cp.async.wait_group 1;");
        } else {
            asm volatile("cp.async.wait_group 0;");
        }
        __syncthreads();

        uint32_t abase = sAb + ((kt & 1) ? 8192u : 0u);
        uint32_t bbase = sBb + ((kt & 1) ? 8192u : 0u);
        #pragma unroll
        for (int kk = 0; kk < 2; kk++) {       // two k16 halves of BK=32
            int kb = kk * 2;                   // chunk base (8 bf16 per chunk)
            uint32_t a[4][4], b[2][4];
            #pragma unroll
            for (int i = 0; i < 4; i++) {
                int r = wm * 64 + i * 16 + (lane & 15);
                int c = kb + (lane >> 4);
                ldsm_x4(abase + r * 64 + ((c ^ (r & 3)) << 4), a[i]);
            }
            #pragma unroll
            for (int j = 0; j < 2; j++) {
                int r = wn * 32 + j * 16 + ((lane & 16) >> 1) + (lane & 7);
                int c = kb + ((lane >> 3) & 1);
                ldsm_x4(bbase + r * 64 + ((c ^ (r & 3)) << 4), b[j]);
            }
            #pragma unroll
            for (int i = 0; i < 4; i++)
                #pragma unroll
                for (int jn = 0; jn < 4; jn++)
                    mma16816(acc[i][jn], a[i], b[jn >> 1] + (jn & 1) * 2);
        }
        __syncthreads();
    }

    // epilogue: add bias, write fp32
    int g = lane >> 2, q = lane & 3;
    #pragma unroll
    for (int i = 0; i < 4; i++) {
        int rr = bm + wm * 64 + i * 16 + g;
        #pragma unroll
        for (int jn = 0; jn < 4; jn++) {
            int cb = bn + wn * 32 + jn * 8 + q * 2;
            float bb0 = bias[cb], bb1 = bias[cb + 1];
            C[(size_t)rr * V_ + cb]       = acc[i][jn][0] + bb0;
            C[(size_t)rr * V_ + cb + 1]   = acc[i][jn][1] + bb1;
            C[(size_t)(rr + 8) * V_ + cb]     = acc[i][jn][2] + bb0;
            C[(size_t)(rr + 8) * V_ + cb + 1] = acc[i][jn][3] + bb1;
        }
    }
}

// ---------------- generic SGEMM: C[M,N] = A[M,K] @ Bw[N,K]^T + bias ----------------
__global__ void __launch_bounds__(256)
k_gemm(const float* __restrict__ A, const float* __restrict__ Bw,
       const float* __restrict__ bias, float* __restrict__ C,
       int M, int N, int K) {
    __shared__ float As[16][128];
    __shared__ float Bs[16][128];
    int tid = threadIdx.x;
    int bm = blockIdx.y * 128, bn = blockIdx.x * 128;
    int tm = (tid >> 4) * 8;
    int tn = (tid & 15) * 8;
    float acc[8][8];
    #pragma unroll
    for (int i = 0; i < 8; i++)
        #pragma unroll
        for (int j = 0; j < 8; j++) acc[i][j] = 0.f;

    for (int k0 = 0; k0 < K; k0 += 16) {
        #pragma unroll
        for (int i = 0; i < 2; i++) {
            int f   = tid * 2 + i;
            int row = f >> 2;
            int col = (f & 3) * 4;
            float4 v = *(const float4*)&A[(size_t)(bm + row) * K + k0 + col];
            As[col+0][row] = v.x; As[col+1][row] = v.y;
            As[col+2][row] = v.z; As[col+3][row] = v.w;
        }
        #pragma unroll
        for (int i = 0; i < 2; i++) {
            int f   = tid * 2 + i;
            int row = f >> 2;
            int col = (f & 3) * 4;
            float4 v = *(const float4*)&Bw[(size_t)(bn + row) * K + k0 + col];
            Bs[col+0][row] = v.x; Bs[col+1][row] = v.y;
            Bs[col+2][row] = v.z; Bs[col+3][row] = v.w;
        }
        __syncthreads();
        #pragma unroll
        for (int k = 0; k < 16; k++) {
            float a[8], b[8];
            float4 a0 = *(const float4*)&As[k][tm];
            float4 a1 = *(const float4*)&As[k][tm+4];
            float4 b0 = *(const float4*)&Bs[k][tn];
            float4 b1 = *(const float4*)&Bs[k][tn+4];
            a[0]=a0.x; a[1]=a0.y; a[2]=a0.z; a[3]=a0.w;
            a[4]=a1.x; a[5]=a1.y; a[6]=a1.z; a[7]=a1.w;
            b[0]=b0.x; b[1]=b0.y; b[2]=b0.z; b[3]=b0.w;
            b[4]=b1.x; b[5]=b1.y; b[6]=b1.z; b[7]=b1.w;
            #pragma unroll
            for (int i = 0; i < 8; i++)
                #pragma unroll
                for (int j = 0; j < 8; j++)
                    acc[i][j] += a[i] * b[j];
        }
        __syncthreads();
    }
    #pragma unroll
    for (int i = 0; i < 8; i++) {
        #pragma unroll
        for (int j = 0; j < 8; j++) {
            float v = acc[i][j];
            if (bias) v += bias[bn + tn + j];
            C[(size_t)(bm + tm + i) * N + bn + tn + j] = v;
        }
    }
}

// ---------------- per-step gates + LSTM pointwise ----------------
__global__ void __launch_bounds__(256)
k_gates(int t, const float* __restrict__ W_hh) {
    __shared__ float h_sh[32][65];
    __shared__ float sg[8][33];
    const float* h_in  = g_h[t & 1];
    float*       h_out = g_h[(t + 1) & 1];
    int tid  = threadIdx.x;
    int r    = tid >> 5, b = tid & 31;
    int ub   = blockIdx.x * 2;
    int gate = r & 3, q = r >> 2;
    int row  = gate * H_ + ub + q;
    const float* Wrow = W_hh + (size_t)row * H_;

    float acc = 0.f;
    for (int kk = 0; kk < H_; kk += 64) {
        #pragma unroll
        for (int i = 0; i < 8; i++) {
            int idx = tid + i * 256;
            int bb = idx >> 6, k = idx & 63;
            h_sh[bb][k] = h_in[bb * H_ + kk + k];
        }
        __syncthreads();
        #pragma unroll
        for (int k = 0; k < 64; k++)
            acc += Wrow[kk + k] * h_sh[b][k];
        __syncthreads();
    }
    float gv = acc + g_X[(size_t)(b * T_ + t) * G4_ + row];
    sg[r][b] = gv;
    __syncthreads();

    if (tid < 64) {
        int q2 = tid >> 5, b2 = tid & 31;
        int u  = ub + q2;
        float iv = sg[q2*4 + 0][b2];
        float fv = sg[q2*4 + 1][b2];
        float gg = sg[q2*4 + 2][b2];
        float ov = sg[q2*4 + 3][b2];
        float si = 1.f / (1.f + expf(-iv));
        float sf = 1.f / (1.f + expf(-fv));
        float so = 1.f / (1.f + expf(-ov));
        float c_old = g_c[b2 * H_ + u];
        float c_new = sf * c_old + si * tanhf(gg);
        float h_new = so * tanhf(c_new);
        g_c[b2 * H_ + u]  = c_new;
        h_out[b2 * H_ + u] = h_new;
    }
}

// ---------------- per-step attention: grid (32 batches, 4 chunks of 128) ----------------
__global__ void __launch_bounds__(256)
k_attn(int t, const float* __restrict__ enc, const int* __restrict__ lens) {
    int b  = blockIdx.x;
    int ec = blockIdx.y;              // 0..3: chunk of 128 cols
    __shared__ float h_sh[H_];
    __shared__ float sc[S_];
    __shared__ float red[40];
    const float* h_cur = g_h[(t + 1) & 1] + b * H_;
    int tid = threadIdx.x;
    for (int i = tid; i < H_; i += 256) h_sh[i] = h_cur[i];
    __syncthreads();

    int warp = tid >> 5, lane = tid & 31;
    for (int s = warp; s < S_; s += 8) {
        const float* pr = g_proj + ((size_t)b * S_ + s) * H_;
        float a = 0.f;
        for (int k = lane; k < H_; k += 32) a += h_sh[k] * pr[k];
        #pragma unroll
        for (int o = 16; o; o >>= 1) a += __shfl_xor_sync(0xFFFFFFFFu, a, o);
        if (lane == 0) sc[s] = a;
    }
    __syncthreads();
    int len = lens[b];
    if (tid < S_ && tid >= len) sc[tid] = -1e9f;
    __syncthreads();

    float m = (tid < S_) ? sc[tid] : -1e30f;
    #pragma unroll
    for (int o = 16; o; o >>= 1) m = fmaxf(m, __shfl_xor_sync(0xFFFFFFFFu, m, o));
    if (lane == 0) red[warp] = m;
    __syncthreads();
    if (tid == 0) {
        float mm = red[0];
        for (int i = 1; i < 8; i++) mm = fmaxf(mm, red[i]);
        red[32] = mm;
    }
    __syncthreads();
    float mx = red[32];

    float p = (tid < S_) ? expf(sc[tid] - mx) : 0.f;
    float ps = p;
    #pragma unroll
    for (int o = 16; o; o >>= 1) ps += __shfl_xor_sync(0xFFFFFFFFu, ps, o);
    if (lane == 0) red[warp] = ps;
    __syncthreads();
    if (tid == 0) {
        float sm = 0.f;
        for (int i = 0; i < 8; i++) sm += red[i];
        red[33] = 1.f / sm;
    }
    __syncthreads();
    if (tid < S_) sc[tid] = p * red[33];
    __syncthreads();

    float* dst = g_hcat + (size_t)(b * T_ + t) * (H_ + ENC_);
    const float* eb = enc + (size_t)b * S_ * ENC_;
    if (tid < 128) {
        int e = ec * 128 + tid;
        float a = 0.f;
        #pragma unroll 8
        for (int s = 0; s < S_; s++) a += sc[s] * eb[(size_t)s * ENC_ + e];
        dst[H_ + e] = a;
        dst[ec * 128 + tid] = h_sh[ec * 128 + tid];
    }
}

// ---------------- launch ----------------
extern "C" void kernel_launch(void* const* d_in, const int* in_sizes, int n_in,
                              void* d_out, int out_size) {
    const int*   gold   = (const int*)  d_in[0];
    const float* enc    = (const float*)d_in[1];
    const int*   lens   = (const int*)  d_in[2];
    const float* h0     = (const float*)d_in[3];
    const float* c0     = (const float*)d_in[4];
    const float* table  = (const float*)d_in[5];
    const float* W_ih   = (const float*)d_in[6];
    const float* W_hh   = (const float*)d_in[7];
    const float* b_ih   = (const float*)d_in[8];
    const float* b_hh   = (const float*)d_in[9];
    const float* Wa     = (const float*)d_in[10];
    const float* Wc_w   = (const float*)d_in[11];
    const float* Wc_b   = (const float*)d_in[12];
    const float* Wo_w   = (const float*)d_in[13];
    const float* Wo_b   = (const float*)d_in[14];
    float* out = (float*)d_out;

    float *p_emb, *p_X, *p_proj, *p_hcat, *p_ho, *p_bias;
    cudaGetSymbolAddress((void**)&p_emb,  g_emb);
    cudaGetSymbolAddress((void**)&p_X,    g_X);
    cudaGetSymbolAddress((void**)&p_proj, g_proj);
    cudaGetSymbolAddress((void**)&p_hcat, g_hcat);
    cudaGetSymbolAddress((void**)&p_ho,   g_ho);
    cudaGetSymbolAddress((void**)&p_bias, g_bias);
    __nv_bfloat16 *p_Abig, *p_Bbig;
    cudaGetSymbolAddress((void**)&p_Abig, g_Abig);
    cudaGetSymbolAddress((void**)&p_Bbig, g_Bbig);

    k_init<<<64, 256>>>(h0, c0, b_ih, b_hh);
    k_embed<<<BT_, 256>>>(gold, table);
    // Wo split can start immediately (independent of the loop)
    k_splitB<<<(V_*H_ + 255)/256, 256>>>(Wo_w);

    // X = emb @ W_ih^T + bias     [2048 x 2048, K=256]
    k_gemm<<<dim3(G4_/128, BT_/128), 256>>>(p_emb, W_ih, p_bias, p_X, BT_, G4_, E_);
    // proj_enc = enc @ Wa^T       [4096 x 512, K=512]
    k_gemm<<<dim3(H_/128, (B_*S_)/128), 256>>>(enc, Wa, nullptr, p_proj, B_*S_, H_, ENC_);

    for (int t = 0; t < T_; t++) {
        k_gates<<<256, 256>>>(t, W_hh);
        k_attn<<<dim3(32, 4), 256>>>(t, enc, lens);
    }

    // HO = [h;ctx] @ Wc_w^T + Wc_b   [2048 x 512, K=1024]
    k_gemm<<<dim3(H_/128, BT_/128), 256>>>(p_hcat, Wc_w, Wc_b, p_ho, BT_, H_, H_+ENC_);
    // split ho into K-concat bf16 operand
    k_splitA<<<(BT_*H_ + 255)/256, 256>>>(p_ho);
    // logits via mma.sync bf16 (error-compensated, K=1536)
    k_hmma<<<dim3(V_/128, BT_/128), 256>>>(p_Abig, p_Bbig, Wo_b, out);
}

// round 9
// speedup vs baseline: 1.9615x; 1.4894x over previous
#include <cuda_runtime.h>
#include <cuda_bf16.h>
#include <math.h>
#include <stdint.h>

#define B_  32
#define T_  64
#define S_  128
#define E_  256
#define H_  512
#define ENC_ 512
#define V_  32000
#define G4_ (4*H_)   // 2048
#define BT_ (B_*T_)  // 2048
#define KBIG 1536    // 3 * H_ : [hoHi|hoHi|hoLo] x [WoHi|WoLo|WoHi]
#define NKIT 48      // KBIG / 32

// ---------------- scratch (static device globals; no allocation) ----------------
__device__ float g_emb [BT_*E_];
__device__ float g_X   [BT_*G4_];
__device__ float g_proj[B_*S_*H_];
__device__ float g_bias[G4_];
__device__ float g_h   [2][B_*H_];
__device__ float g_c   [B_*H_];
__device__ float g_hcat[BT_*(H_+ENC_)];
__device__ float g_ho  [BT_*H_];
__device__ float g_sc  [B_*S_];           // raw attention scores per step
__device__ unsigned g_bar;                // global barrier counter (reset by k_init)
// K-concatenated bf16 operands for the HMMA logits GEMM
__device__ __align__(128) __nv_bfloat16 g_Abig[BT_*KBIG];        // 6.3 MB
__device__ __align__(128) __nv_bfloat16 g_Bbig[(size_t)V_*KBIG]; // 98 MB

// ---------------- init: state + combined bias + barrier reset ----------------
__global__ void k_init(const float* __restrict__ h0, const float* __restrict__ c0,
                       const float* __restrict__ b_ih, const float* __restrict__ b_hh) {
    int i = blockIdx.x * blockDim.x + threadIdx.x;
    if (i == 0) g_bar = 0u;
    if (i < B_*H_) { g_h[0][i] = h0[i]; g_c[i] = c0[i]; }
    if (i < G4_)   g_bias[i] = b_ih[i] + b_hh[i];
}

// ---------------- embedding gather ----------------
__global__ void k_embed(const int* __restrict__ tok, const float* __restrict__ table) {
    int bt = blockIdx.x;
    int e  = threadIdx.x;
    g_emb[bt*E_ + e] = table[tok[bt]*E_ + e];
}

// ---------------- fp32 -> bf16 hi/lo splits into K-concat layouts ----------------
__global__ void k_splitA(const float* __restrict__ src) {   // ho [2048,512]
    int i = blockIdx.x * blockDim.x + threadIdx.x;
    if (i < BT_*H_) {
        int row = i >> 9, k = i & 511;
        float a = src[i];
        __nv_bfloat16 h = __float2bfloat16(a);
        __nv_bfloat16 l = __float2bfloat16(a - __bfloat162float(h));
        size_t b = (size_t)row * KBIG;
        g_Abig[b + k]        = h;
        g_Abig[b + 512 + k]  = h;
        g_Abig[b + 1024 + k] = l;
    }
}
__global__ void k_splitB(const float* __restrict__ src) {   // Wo_w [32000,512]
    int i = blockIdx.x * blockDim.x + threadIdx.x;
    if (i < V_*H_) {
        int row = i >> 9, k = i & 511;
        float a = src[i];
        __nv_bfloat16 h = __float2bfloat16(a);
        __nv_bfloat16 l = __float2bfloat16(a - __bfloat162float(h));
        size_t b = (size_t)row * KBIG;
        g_Bbig[b + k]        = h;
        g_Bbig[b + 512 + k]  = l;
        g_Bbig[b + 1024 + k] = h;
    }
}

// ---------------- mma.sync helpers ----------------
__device__ __forceinline__ void ldsm_x4(uint32_t addr, uint32_t* r) {
    asm volatile("ldmatrix.sync.aligned.m8n8.x4.shared.b16 {%0,%1,%2,%3}, [%4];"
        : "=r"(r[0]), "=r"(r[1]), "=r"(r[2]), "=r"(r[3]) : "r"(addr));
}
__device__ __forceinline__ void mma16816(float* d, const uint32_t* a, const uint32_t* b) {
    asm volatile("mma.sync.aligned.m16n8k16.row.col.f32.bf16.bf16.f32 "
        "{%0,%1,%2,%3}, {%4,%5,%6,%7}, {%8,%9}, {%0,%1,%2,%3};"
        : "+f"(d[0]), "+f"(d[1]), "+f"(d[2]), "+f"(d[3])
        : "r"(a[0]), "r"(a[1]), "r"(a[2]), "r"(a[3]), "r"(b[0]), "r"(b[1]));
}
__device__ __forceinline__ void cp16(uint32_t dst, const void* src) {
    asm volatile("cp.async.cg.shared.global [%0], [%1], 16;" :: "r"(dst), "l"(src));
}
// conflict-free chunk swizzle: 64B rows of 4x16B chunks; all 8 rows of an
// ldmatrix phase hit distinct 16B bank-groups: (r*4 + (c ^ ((r>>1)&3))) % 8
#define SWZ(r, c) ((uint32_t)((r) * 64 + (((c) ^ (((r) >> 1) & 3)) << 4)))

// ---------------- HMMA logits GEMM ----------------
// C[2048, 32000] = A'[2048,1536] @ B'[32000,1536]^T + bias
// CTA 128x128, 8 warps (2m x 4n), warp 64x32, BK=32, double-buffered cp.async.
__global__ void __launch_bounds__(256)
k_hmma(const __nv_bfloat16* __restrict__ A, const __nv_bfloat16* __restrict__ Bw,
       const float* __restrict__ bias, float* __restrict__ C) {
    __shared__ __align__(128) __nv_bfloat16 sA[2][128*32];
    __shared__ __align__(128) __nv_bfloat16 sB[2][128*32];
    int tid = threadIdx.x, lane = tid & 31, warp = tid >> 5;
    int wm = warp >> 2, wn = warp & 3;
    int bm = blockIdx.y * 128, bn = blockIdx.x * 128;
    uint32_t sAb = (uint32_t)__cvta_generic_to_shared(sA);
    uint32_t sBb = (uint32_t)__cvta_generic_to_shared(sB);

    float acc[4][4][4];
    #pragma unroll
    for (int i = 0; i < 4; i++)
        #pragma unroll
        for (int j = 0; j < 4; j++)
            #pragma unroll
            for (int v = 0; v < 4; v++) acc[i][j][v] = 0.f;

    int ch0 = tid * 2, ch1 = tid * 2 + 1;
    int r0 = ch0 >> 2, c0 = ch0 & 3;
    int r1 = ch1 >> 2, c1 = ch1 & 3;
    uint32_t dA0 = SWZ(r0, c0);
    uint32_t dA1 = SWZ(r1, c1);

    {
        cp16(sAb + dA0, &A[(size_t)(bm + r0) * KBIG + c0 * 8]);
        cp16(sAb + dA1, &A[(size_t)(bm + r1) * KBIG + c1 * 8]);
        cp16(sBb + dA0, &Bw[(size_t)(bn + r0) * KBIG + c0 * 8]);
        cp16(sBb + dA1, &Bw[(size_t)(bn + r1) * KBIG + c1 * 8]);
        asm volatile("cp.async.commit_group;");
    }

    #pragma unroll 1
    for (int kt = 0; kt < NKIT; kt++) {
        if (kt + 1 < NKIT) {
            int k0 = (kt + 1) * 32;
            uint32_t so = ((kt + 1) & 1) ? 8192u : 0u;
            cp16(sAb + so + dA0, &A[(size_t)(bm + r0) * KBIG + k0 + c0 * 8]);
            cp16(sAb + so + dA1, &A[(size_t)(bm + r1) * KBIG + k0 + c1 * 8]);
            cp16(sBb + so + dA0, &Bw[(size_t)(bn + r0) * KBIG + k0 + c0 * 8]);
            cp16(sBb + so + dA1, &Bw[(size_t)(bn + r1) * KBIG + k0 + c1 * 8]);
            asm volatile("cp.async.commit_group;");
            asm volatile("cp.async.wait_group 1;");
        } else {
            asm volatile("cp.async.wait_group 0;");
        }
        __syncthreads();

        uint32_t abase = sAb + ((kt & 1) ? 8192u : 0u);
        uint32_t bbase = sBb + ((kt & 1) ? 8192u : 0u);
        #pragma unroll
        for (int kk = 0; kk < 2; kk++) {
            int kb = kk * 2;
            uint32_t a[4][4], b[2][4];
            #pragma unroll
            for (int i = 0; i < 4; i++) {
                int r = wm * 64 + i * 16 + (lane & 15);
                int c = kb + (lane >> 4);
                ldsm_x4(abase + SWZ(r, c), a[i]);
            }
            #pragma unroll
            for (int j = 0; j < 2; j++) {
                int r = wn * 32 + j * 16 + ((lane & 16) >> 1) + (lane & 7);
                int c = kb + ((lane >> 3) & 1);
                ldsm_x4(bbase + SWZ(r, c), b[j]);
            }
            #pragma unroll
            for (int i = 0; i < 4; i++)
                #pragma unroll
                for (int jn = 0; jn < 4; jn++)
                    mma16816(acc[i][jn], a[i], b[jn >> 1] + (jn & 1) * 2);
        }
        __syncthreads();
    }

    int g = lane >> 2, q = lane & 3;
    #pragma unroll
    for (int i = 0; i < 4; i++) {
        int rr = bm + wm * 64 + i * 16 + g;
        #pragma unroll
        for (int jn = 0; jn < 4; jn++) {
            int cb = bn + wn * 32 + jn * 8 + q * 2;
            float bb0 = bias[cb], bb1 = bias[cb + 1];
            C[(size_t)rr * V_ + cb]           = acc[i][jn][0] + bb0;
            C[(size_t)rr * V_ + cb + 1]       = acc[i][jn][1] + bb1;
            C[(size_t)(rr + 8) * V_ + cb]     = acc[i][jn][2] + bb0;
            C[(size_t)(rr + 8) * V_ + cb + 1] = acc[i][jn][3] + bb1;
        }
    }
}

// ---------------- generic SGEMM: C[M,N] = A[M,K] @ Bw[N,K]^T + bias ----------------
__global__ void __launch_bounds__(256)
k_gemm(const float* __restrict__ A, const float* __restrict__ Bw,
       const float* __restrict__ bias, float* __restrict__ C,
       int M, int N, int K) {
    __shared__ float As[16][128];
    __shared__ float Bs[16][128];
    int tid = threadIdx.x;
    int bm = blockIdx.y * 128, bn = blockIdx.x * 128;
    int tm = (tid >> 4) * 8;
    int tn = (tid & 15) * 8;
    float acc[8][8];
    #pragma unroll
    for (int i = 0; i < 8; i++)
        #pragma unroll
        for (int j = 0; j < 8; j++) acc[i][j] = 0.f;

    for (int k0 = 0; k0 < K; k0 += 16) {
        #pragma unroll
        for (int i = 0; i < 2; i++) {
            int f   = tid * 2 + i;
            int row = f >> 2;
            int col = (f & 3) * 4;
            float4 v = *(const float4*)&A[(size_t)(bm + row) * K + k0 + col];
            As[col+0][row] = v.x; As[col+1][row] = v.y;
            As[col+2][row] = v.z; As[col+3][row] = v.w;
        }
        #pragma unroll
        for (int i = 0; i < 2; i++) {
            int f   = tid * 2 + i;
            int row = f >> 2;
            int col = (f & 3) * 4;
            float4 v = *(const float4*)&Bw[(size_t)(bn + row) * K + k0 + col];
            Bs[col+0][row] = v.x; Bs[col+1][row] = v.y;
            Bs[col+2][row] = v.z; Bs[col+3][row] = v.w;
        }
        __syncthreads();
        #pragma unroll
        for (int k = 0; k < 16; k++) {
            float a[8], b[8];
            float4 a0 = *(const float4*)&As[k][tm];
            float4 a1 = *(const float4*)&As[k][tm+4];
            float4 b0 = *(const float4*)&Bs[k][tn];
            float4 b1 = *(const float4*)&Bs[k][tn+4];
            a[0]=a0.x; a[1]=a0.y; a[2]=a0.z; a[3]=a0.w;
            a[4]=a1.x; a[5]=a1.y; a[6]=a1.z; a[7]=a1.w;
            b[0]=b0.x; b[1]=b0.y; b[2]=b0.z; b[3]=b0.w;
            b[4]=b1.x; b[5]=b1.y; b[6]=b1.z; b[7]=b1.w;
            #pragma unroll
            for (int i = 0; i < 8; i++)
                #pragma unroll
                for (int j = 0; j < 8; j++)
                    acc[i][j] += a[i] * b[j];
        }
        __syncthreads();
    }
    #pragma unroll
    for (int i = 0; i < 8; i++) {
        #pragma unroll
        for (int j = 0; j < 8; j++) {
            float v = acc[i][j];
            if (bias) v += bias[bn + tn + j];
            C[(size_t)(bm + tm + i) * N + bn + tn + j] = v;
        }
    }
}

// ---------------- persistent fused decode loop ----------------
// 256 CTAs x 256 threads, guaranteed co-resident (<= 2 CTAs/SM x 148 SMs).
// Per step: Phase A gates/LSTM -> gbar -> Phase B scores -> gbar -> Phase C
// softmax+ctx -> gbar. Global barrier: counter arrive + bounded spin (hang-proof).
__device__ __forceinline__ void gbar_arrive_wait(unsigned target) {
    __syncthreads();
    if (threadIdx.x == 0) {
        __threadfence();
        atomicAdd(&g_bar, 1u);
        for (int i = 0; i < (1 << 22); i++) {
            if (*(volatile unsigned*)&g_bar >= target) break;
        }
        __threadfence();
    }
    __syncthreads();
}

__global__ void __launch_bounds__(256, 2)
k_loop(const float* __restrict__ W_hh, const float* __restrict__ enc,
       const int* __restrict__ lens) {
    __shared__ float w_sh[8][H_];      // 16 KB: this block's 8 W_hh rows
    __shared__ float h_sh[32][65];     // gates h staging
    __shared__ float sg[8][33];        // gate values
    __shared__ float hb_sh[H_];        // h[b] for scores
    __shared__ float sc_sh[S_];        // scores / att weights
    __shared__ float red[34];
    __shared__ float part[4][64];      // ctx partials
    int tid = threadIdx.x;
    int bid = blockIdx.x;
    int ub  = bid * 2;
    int warp = tid >> 5, lane = tid & 31;

    // cache W_hh rows once for all 64 steps: warp r uses w_sh[r],
    // row = (r&3)*H + ub + (r>>2)
    for (int rr = 0; rr < 8; rr++) {
        int row = (rr & 3) * H_ + ub + (rr >> 2);
        for (int k = tid; k < H_; k += 256)
            w_sh[rr][k] = W_hh[(size_t)row * H_ + k];
    }
    __syncthreads();

    int b2 = bid >> 3, j = bid & 7;    // phase B/C decomposition
    int len = lens[b2];
    unsigned nb = 0;

    for (int t = 0; t < T_; t++) {
        // ---- Phase A: gates + LSTM pointwise ----
        {
            const float* h_in  = g_h[t & 1];
            float*       h_out = g_h[(t + 1) & 1];
            int bb = lane;
            float acc = 0.f;
            for (int kk = 0; kk < H_; kk += 64) {
                #pragma unroll
                for (int i = 0; i < 8; i++) {
                    int idx = tid + i * 256;
                    int b3 = idx >> 6, k = idx & 63;
                    h_sh[b3][k] = h_in[b3 * H_ + kk + k];
                }
                __syncthreads();
                #pragma unroll
                for (int k = 0; k < 64; k++)
                    acc += w_sh[warp][kk + k] * h_sh[bb][k];
                __syncthreads();
            }
            int row = (warp & 3) * H_ + ub + (warp >> 2);
            sg[warp][bb] = acc + g_X[(size_t)(bb * T_ + t) * G4_ + row];
            __syncthreads();
            if (tid < 64) {
                int q2 = tid >> 5, b3 = tid & 31;
                int u  = ub + q2;
                float iv = sg[q2*4 + 0][b3];
                float fv = sg[q2*4 + 1][b3];
                float gg = sg[q2*4 + 2][b3];
                float ov = sg[q2*4 + 3][b3];
                float si = 1.f / (1.f + expf(-iv));
                float sf = 1.f / (1.f + expf(-fv));
                float so = 1.f / (1.f + expf(-ov));
                float c_old = g_c[b3 * H_ + u];
                float c_new = sf * c_old + si * tanhf(gg);
                g_c[b3 * H_ + u]   = c_new;
                h_out[b3 * H_ + u] = so * tanhf(c_new);
            }
        }
        nb++; gbar_arrive_wait(nb * 256);

        // ---- Phase B: scores for s in [j*16, j*16+16) of batch b2 ----
        {
            const float* hn = g_h[(t + 1) & 1] + b2 * H_;
            for (int i = tid; i < H_; i += 256) hb_sh[i] = hn[i];
            __syncthreads();
            int s0 = j * 16 + warp * 2;
            const float* p0 = g_proj + ((size_t)b2 * S_ + s0) * H_;
            const float* p1 = p0 + H_;
            float a0 = 0.f, a1 = 0.f;
            #pragma unroll 4
            for (int k = lane; k < H_; k += 32) {
                float hv = hb_sh[k];
                a0 += hv * p0[k];
                a1 += hv * p1[k];
            }
            #pragma unroll
            for (int o = 16; o; o >>= 1) {
                a0 += __shfl_xor_sync(0xFFFFFFFFu, a0, o);
                a1 += __shfl_xor_sync(0xFFFFFFFFu, a1, o);
            }
            if (lane == 0) { g_sc[b2 * S_ + s0] = a0; g_sc[b2 * S_ + s0 + 1] = a1; }
        }
        nb++; gbar_arrive_wait(nb * 256);

        // ---- Phase C: softmax (redundant per 8 blocks, cheap) + ctx chunk ----
        {
            if (tid < S_) {
                float v = g_sc[b2 * S_ + tid];
                sc_sh[tid] = (tid < len) ? v : -1e9f;
            }
            __syncthreads();
            float m = (tid < S_) ? sc_sh[tid] : -1e30f;
            #pragma unroll
            for (int o = 16; o; o >>= 1) m = fmaxf(m, __shfl_xor_sync(0xFFFFFFFFu, m, o));
            if (lane == 0) red[warp] = m;
            __syncthreads();
            if (tid == 0) {
                float mm = red[0];
                for (int i = 1; i < 8; i++) mm = fmaxf(mm, red[i]);
                red[32] = mm;
            }
            __syncthreads();
            float mx = red[32];
            float p = (tid < S_) ? expf(sc_sh[tid] - mx) : 0.f;
            float ps = p;
            #pragma unroll
            for (int o = 16; o; o >>= 1) ps += __shfl_xor_sync(0xFFFFFFFFu, ps, o);
            if (lane == 0) red[warp] = ps;
            __syncthreads();
            if (tid == 0) {
                float sm = 0.f;
                for (int i = 0; i < 8; i++) sm += red[i];
                red[33] = 1.f / sm;
            }
            __syncthreads();
            if (tid < S_) sc_sh[tid] = p * red[33];
            __syncthreads();

            // ctx cols e in [j*64, j*64+64); thread = (p-quarter, col)
            int cc = tid & 63, pq = tid >> 6;
            int e  = j * 64 + cc;
            const float* eb = enc + ((size_t)b2 * S_ + pq * 32) * ENC_ + e;
            float a = 0.f;
            #pragma unroll 8
            for (int s = 0; s < 32; s++) a += sc_sh[pq * 32 + s] * eb[(size_t)s * ENC_];
            part[pq][cc] = a;
            __syncthreads();
            if (tid < 64) {
                float cx = part[0][tid] + part[1][tid] + part[2][tid] + part[3][tid];
                float* dst = g_hcat + (size_t)(b2 * T_ + t) * (H_ + ENC_);
                dst[H_ + j * 64 + tid] = cx;
                dst[j * 64 + tid] = g_h[(t + 1) & 1][b2 * H_ + j * 64 + tid];
            }
        }
        nb++; gbar_arrive_wait(nb * 256);
    }
}

// ---------------- launch ----------------
extern "C" void kernel_launch(void* const* d_in, const int* in_sizes, int n_in,
                              void* d_out, int out_size) {
    const int*   gold   = (const int*)  d_in[0];
    const float* enc    = (const float*)d_in[1];
    const int*   lens   = (const int*)  d_in[2];
    const float* h0     = (const float*)d_in[3];
    const float* c0     = (const float*)d_in[4];
    const float* table  = (const float*)d_in[5];
    const float* W_ih   = (const float*)d_in[6];
    const float* W_hh   = (const float*)d_in[7];
    const float* b_ih   = (const float*)d_in[8];
    const float* b_hh   = (const float*)d_in[9];
    const float* Wa     = (const float*)d_in[10];
    const float* Wc_w   = (const float*)d_in[11];
    const float* Wc_b   = (const float*)d_in[12];
    const float* Wo_w   = (const float*)d_in[13];
    const float* Wo_b   = (const float*)d_in[14];
    float* out = (float*)d_out;

    float *p_emb, *p_X, *p_proj, *p_hcat, *p_ho, *p_bias;
    cudaGetSymbolAddress((void**)&p_emb,  g_emb);
    cudaGetSymbolAddress((void**)&p_X,    g_X);
    cudaGetSymbolAddress((void**)&p_proj, g_proj);
    cudaGetSymbolAddress((void**)&p_hcat, g_hcat);
    cudaGetSymbolAddress((void**)&p_ho,   g_ho);
    cudaGetSymbolAddress((void**)&p_bias, g_bias);
    __nv_bfloat16 *p_Abig, *p_Bbig;
    cudaGetSymbolAddress((void**)&p_Abig, g_Abig);
    cudaGetSymbolAddress((void**)&p_Bbig, g_Bbig);

    k_init<<<64, 256>>>(h0, c0, b_ih, b_hh);
    k_embed<<<BT_, 256>>>(gold, table);
    k_splitB<<<(V_*H_ + 255)/256, 256>>>(Wo_w);

    // X = emb @ W_ih^T + bias     [2048 x 2048, K=256]
    k_gemm<<<dim3(G4_/128, BT_/128), 256>>>(p_emb, W_ih, p_bias, p_X, BT_, G4_, E_);
    // proj_enc = enc @ Wa^T       [4096 x 512, K=512]
    k_gemm<<<dim3(H_/128, (B_*S_)/128), 256>>>(enc, Wa, nullptr, p_proj, B_*S_, H_, ENC_);

    // fused persistent decode loop (replaces 128 per-step launches)
    k_loop<<<256, 256>>>(W_hh, enc, lens);

    // HO = [h;ctx] @ Wc_w^T + Wc_b   [2048 x 512, K=1024]
    k_gemm<<<dim3(H_/128, BT_/128), 256>>>(p_hcat, Wc_w, Wc_b, p_ho, BT_, H_, H_+ENC_);
    // split ho into K-concat bf16 operand
    k_splitA<<<(BT_*H_ + 255)/256, 256>>>(p_ho);
    // logits via mma.sync bf16 (error-compensated, K=1536)
    k_hmma<<<dim3(V_/128, BT_/128), 256>>>(p_Abig, p_Bbig, Wo_b, out);
}

// round 11
// speedup vs baseline: 2.0546x; 1.0474x over previous
#include <cuda_runtime.h>
#include <cuda_bf16.h>
#include <math.h>
#include <stdint.h>

#define B_  32
#define T_  64
#define S_  128
#define E_  256
#define H_  512
#define ENC_ 512
#define V_  32000
#define G4_ (4*H_)   // 2048
#define BT_ (B_*T_)  // 2048
#define KBIG 1536    // 3 * H_ : [hoHi|hoHi|hoLo] x [WoHi|WoLo|WoHi]
#define NKIT 48      // KBIG / 32

// ---------------- scratch (static device globals; no allocation) ----------------
__device__ float g_emb [BT_*E_];
__device__ float g_X   [BT_*G4_];
__device__ float g_proj[B_*S_*H_];
__device__ float g_bias[G4_];
__device__ float g_h   [2][B_*H_];
__device__ float g_c   [B_*H_];
__device__ float g_hcat[BT_*(H_+ENC_)];
__device__ float g_ho  [BT_*H_];
__device__ float g_sc  [B_*S_];           // raw attention scores per step
__device__ unsigned g_bar;                // global barrier counter (reset by k_init)
// K-concatenated bf16 operands for the HMMA logits GEMM
__device__ __align__(128) __nv_bfloat16 g_Abig[BT_*KBIG];        // 6.3 MB
__device__ __align__(128) __nv_bfloat16 g_Bbig[(size_t)V_*KBIG]; // 98 MB

// ---------------- init ----------------
__global__ void k_init(const float* __restrict__ h0, const float* __restrict__ c0,
                       const float* __restrict__ b_ih, const float* __restrict__ b_hh) {
    int i = blockIdx.x * blockDim.x + threadIdx.x;
    if (i == 0) g_bar = 0u;
    if (i < B_*H_) { g_h[0][i] = h0[i]; g_c[i] = c0[i]; }
    if (i < G4_)   g_bias[i] = b_ih[i] + b_hh[i];
}

// ---------------- embedding gather ----------------
__global__ void k_embed(const int* __restrict__ tok, const float* __restrict__ table) {
    int bt = blockIdx.x;
    int e  = threadIdx.x;
    g_emb[bt*E_ + e] = table[tok[bt]*E_ + e];
}

// ---------------- fp32 -> bf16 hi/lo splits into K-concat layouts ----------------
__global__ void k_splitA(const float* __restrict__ src) {   // ho [2048,512]
    int i = blockIdx.x * blockDim.x + threadIdx.x;
    if (i < BT_*H_) {
        int row = i >> 9, k = i & 511;
        float a = src[i];
        __nv_bfloat16 h = __float2bfloat16(a);
        __nv_bfloat16 l = __float2bfloat16(a - __bfloat162float(h));
        size_t b = (size_t)row * KBIG;
        g_Abig[b + k]        = h;
        g_Abig[b + 512 + k]  = h;
        g_Abig[b + 1024 + k] = l;
    }
}
__global__ void k_splitB(const float* __restrict__ src) {   // Wo_w [32000,512]
    int i = blockIdx.x * blockDim.x + threadIdx.x;
    if (i < V_*H_) {
        int row = i >> 9, k = i & 511;
        float a = src[i];
        __nv_bfloat16 h = __float2bfloat16(a);
        __nv_bfloat16 l = __float2bfloat16(a - __bfloat162float(h));
        size_t b = (size_t)row * KBIG;
        g_Bbig[b + k]        = h;
        g_Bbig[b + 512 + k]  = l;
        g_Bbig[b + 1024 + k] = h;
    }
}

// ---------------- mma.sync helpers ----------------
__device__ __forceinline__ void ldsm_x4(uint32_t addr, uint32_t* r) {
    asm volatile("ldmatrix.sync.aligned.m8n8.x4.shared.b16 {%0,%1,%2,%3}, [%4];"
        : "=r"(r[0]), "=r"(r[1]), "=r"(r[2]), "=r"(r[3]) : "r"(addr));
}
__device__ __forceinline__ void mma16816(float* d, const uint32_t* a, const uint32_t* b) {
    asm volatile("mma.sync.aligned.m16n8k16.row.col.f32.bf16.bf16.f32 "
        "{%0,%1,%2,%3}, {%4,%5,%6,%7}, {%8,%9}, {%0,%1,%2,%3};"
        : "+f"(d[0]), "+f"(d[1]), "+f"(d[2]), "+f"(d[3])
        : "r"(a[0]), "r"(a[1]), "r"(a[2]), "r"(a[3]), "r"(b[0]), "r"(b[1]));
}
__device__ __forceinline__ void cp16(uint32_t dst, const void* src) {
    asm volatile("cp.async.cg.shared.global [%0], [%1], 16;" :: "r"(dst), "l"(src));
}
// conflict-free chunk swizzle: 64B rows of 4x16B chunks
#define SWZ(r, c) ((uint32_t)((r) * 64 + (((c) ^ (((r) >> 1) & 3)) << 4)))

// ---------------- HMMA logits GEMM (3-stage, 128x256 CTA, 64x64 warp) ----------
// C[2048, 32000] = A'[2048,1536] @ B'[32000,1536]^T + bias
#define HS_A 8192            // 128 rows x 64B per stage
#define HS_B 16384           // 256 rows x 64B per stage
#define HS_BOFF (3 * HS_A)   // B region base
#define HS_TOTAL (3 * HS_A + 3 * HS_B)   // 73728

__global__ void __launch_bounds__(256, 1)
k_hmma(const __nv_bfloat16* __restrict__ A, const __nv_bfloat16* __restrict__ Bw,
       const float* __restrict__ bias, float* __restrict__ C) {
    extern __shared__ char hsm[];
    int tid = threadIdx.x, lane = tid & 31, warp = tid >> 5;
    int wm = warp >> 2, wn = warp & 3;          // 2 x 4 warp grid
    int bm = blockIdx.y * 128, bn = blockIdx.x * 256;
    uint32_t sb = (uint32_t)__cvta_generic_to_shared(hsm);

    float acc[4][8][4];
    #pragma unroll
    for (int i = 0; i < 4; i++)
        #pragma unroll
        for (int j = 0; j < 8; j++)
            #pragma unroll
            for (int v = 0; v < 4; v++) acc[i][j][v] = 0.f;

    // per-stage loader: A 512 chunks (2/thread), B 1024 chunks (4/thread)
    auto load_stage = [&](int stage, int k0) {
        uint32_t sa = sb + stage * HS_A;
        uint32_t sbb = sb + HS_BOFF + stage * HS_B;
        #pragma unroll
        for (int i = 0; i < 2; i++) {
            int ch = tid + i * 256;
            int r = ch >> 2, c = ch & 3;
            cp16(sa + SWZ(r, c), &A[(size_t)(bm + r) * KBIG + k0 + c * 8]);
        }
        #pragma unroll
        for (int i = 0; i < 4; i++) {
            int ch = tid + i * 256;
            int r = ch >> 2, c = ch & 3;
            cp16(sbb + SWZ(r, c), &Bw[(size_t)(bn + r) * KBIG + k0 + c * 8]);
        }
        asm volatile("cp.async.commit_group;");
    };

    load_stage(0, 0);
    load_stage(1, 32);

    #pragma unroll 1
    for (int kt = 0; kt < NKIT; kt++) {
        if (kt == NKIT - 1) asm volatile("cp.async.wait_group 0;");
        else                asm volatile("cp.async.wait_group 1;");
        __syncthreads();

        // prefetch stage kt+2 (buffer (kt+2)%3: consumed at kt-1, safe after sync)
        if (kt + 2 < NKIT) load_stage((kt + 2) % 3, (kt + 2) * 32);

        int st = kt % 3;
        uint32_t abase = sb + st * HS_A;
        uint32_t bbase = sb + HS_BOFF + st * HS_B;
        #pragma unroll
        for (int kk = 0; kk < 2; kk++) {
            int kb = kk * 2;
            uint32_t a[4][4], b[4][4];
            #pragma unroll
            for (int i = 0; i < 4; i++) {
                int r = wm * 64 + i * 16 + (lane & 15);
                int c = kb + (lane >> 4);
                ldsm_x4(abase + SWZ(r, c), a[i]);
            }
            #pragma unroll
            for (int j = 0; j < 4; j++) {
                int r = wn * 64 + j * 16 + ((lane & 16) >> 1) + (lane & 7);
                int c = kb + ((lane >> 3) & 1);
                ldsm_x4(bbase + SWZ(r, c), b[j]);
            }
            #pragma unroll
            for (int i = 0; i < 4; i++)
                #pragma unroll
                for (int jn = 0; jn < 8; jn++)
                    mma16816(acc[i][jn], a[i], b[jn >> 1] + (jn & 1) * 2);
        }
        __syncthreads();
    }

    // epilogue: add bias, write fp32
    int g = lane >> 2, q = lane & 3;
    #pragma unroll
    for (int i = 0; i < 4; i++) {
        int rr = bm + wm * 64 + i * 16 + g;
        #pragma unroll
        for (int jn = 0; jn < 8; jn++) {
            int cb = bn + wn * 64 + jn * 8 + q * 2;
            float bb0 = bias[cb], bb1 = bias[cb + 1];
            C[(size_t)rr * V_ + cb]           = acc[i][jn][0] + bb0;
            C[(size_t)rr * V_ + cb + 1]       = acc[i][jn][1] + bb1;
            C[(size_t)(rr + 8) * V_ + cb]     = acc[i][jn][2] + bb0;
            C[(size_t)(rr + 8) * V_ + cb + 1] = acc[i][jn][3] + bb1;
        }
    }
}

// ---------------- generic SGEMM: C[M,N] = A[M,K] @ Bw[N,K]^T + bias ----------------
__global__ void __launch_bounds__(256)
k_gemm(const float* __restrict__ A, const float* __restrict__ Bw,
       const float* __restrict__ bias, float* __restrict__ C,
       int M, int N, int K) {
    __shared__ float As[16][128];
    __shared__ float Bs[16][128];
    int tid = threadIdx.x;
    int bm = blockIdx.y * 128, bn = blockIdx.x * 128;
    int tm = (tid >> 4) * 8;
    int tn = (tid & 15) * 8;
    float acc[8][8];
    #pragma unroll
    for (int i = 0; i < 8; i++)
        #pragma unroll
        for (int j = 0; j < 8; j++) acc[i][j] = 0.f;

    for (int k0 = 0; k0 < K; k0 += 16) {
        #pragma unroll
        for (int i = 0; i < 2; i++) {
            int f   = tid * 2 + i;
            int row = f >> 2;
            int col = (f & 3) * 4;
            float4 v = *(const float4*)&A[(size_t)(bm + row) * K + k0 + col];
            As[col+0][row] = v.x; As[col+1][row] = v.y;
            As[col+2][row] = v.z; As[col+3][row] = v.w;
        }
        #pragma unroll
        for (int i = 0; i < 2; i++) {
            int f   = tid * 2 + i;
            int row = f >> 2;
            int col = (f & 3) * 4;
            float4 v = *(const float4*)&Bw[(size_t)(bn + row) * K + k0 + col];
            Bs[col+0][row] = v.x; Bs[col+1][row] = v.y;
            Bs[col+2][row] = v.z; Bs[col+3][row] = v.w;
        }
        __syncthreads();
        #pragma unroll
        for (int k = 0; k < 16; k++) {
            float a[8], b[8];
            float4 a0 = *(const float4*)&As[k][tm];
            float4 a1 = *(const float4*)&As[k][tm+4];
            float4 b0 = *(const float4*)&Bs[k][tn];
            float4 b1 = *(const float4*)&Bs[k][tn+4];
            a[0]=a0.x; a[1]=a0.y; a[2]=a0.z; a[3]=a0.w;
            a[4]=a1.x; a[5]=a1.y; a[6]=a1.z; a[7]=a1.w;
            b[0]=b0.x; b[1]=b0.y; b[2]=b0.z; b[3]=b0.w;
            b[4]=b1.x; b[5]=b1.y; b[6]=b1.z; b[7]=b1.w;
            #pragma unroll
            for (int i = 0; i < 8; i++)
                #pragma unroll
                for (int j = 0; j < 8; j++)
                    acc[i][j] += a[i] * b[j];
        }
        __syncthreads();
    }
    #pragma unroll
    for (int i = 0; i < 8; i++) {
        #pragma unroll
        for (int j = 0; j < 8; j++) {
            float v = acc[i][j];
            if (bias) v += bias[bn + tn + j];
            C[(size_t)(bm + tm + i) * N + bn + tn + j] = v;
        }
    }
}

// ---------------- persistent fused decode loop ----------------
__device__ __forceinline__ void gbar_arrive_wait(unsigned target) {
    __syncthreads();
    if (threadIdx.x == 0) {
        __threadfence();
        atomicAdd(&g_bar, 1u);
        for (int i = 0; i < (1 << 22); i++) {
            if (*(volatile unsigned*)&g_bar >= target) break;
        }
        __threadfence();
    }
    __syncthreads();
}

__global__ void __launch_bounds__(256, 2)
k_loop(const float* __restrict__ W_hh, const float* __restrict__ enc,
       const int* __restrict__ lens) {
    __shared__ float w_sh[8][H_];
    __shared__ float h_sh[32][65];
    __shared__ float sg[8][33];
    __shared__ float hb_sh[H_];
    __shared__ float sc_sh[S_];
    __shared__ float red[34];
    __shared__ float part[4][64];
    int tid = threadIdx.x;
    int bid = blockIdx.x;
    int ub  = bid * 2;
    int warp = tid >> 5, lane = tid & 31;

    for (int rr = 0; rr < 8; rr++) {
        int row = (rr & 3) * H_ + ub + (rr >> 2);
        for (int k = tid; k < H_; k += 256)
            w_sh[rr][k] = W_hh[(size_t)row * H_ + k];
    }
    __syncthreads();

    int b2 = bid >> 3, j = bid & 7;
    int len = lens[b2];
    unsigned nb = 0;

    for (int t = 0; t < T_; t++) {
        // ---- Phase A: gates + LSTM pointwise ----
        {
            const float* h_in  = g_h[t & 1];
            float*       h_out = g_h[(t + 1) & 1];
            int bb = lane;
            float acc = 0.f;
            for (int kk = 0; kk < H_; kk += 64) {
                #pragma unroll
                for (int i = 0; i < 8; i++) {
                    int idx = tid + i * 256;
                    int b3 = idx >> 6, k = idx & 63;
                    h_sh[b3][k] = h_in[b3 * H_ + kk + k];
                }
                __syncthreads();
                #pragma unroll
                for (int k = 0; k < 64; k++)
                    acc += w_sh[warp][kk + k] * h_sh[bb][k];
                __syncthreads();
            }
            int row = (warp & 3) * H_ + ub + (warp >> 2);
            sg[warp][bb] = acc + g_X[(size_t)(bb * T_ + t) * G4_ + row];
            __syncthreads();
            if (tid < 64) {
                int q2 = tid >> 5, b3 = tid & 31;
                int u  = ub + q2;
                float iv = sg[q2*4 + 0][b3];
                float fv = sg[q2*4 + 1][b3];
                float gg = sg[q2*4 + 2][b3];
                float ov = sg[q2*4 + 3][b3];
                float si = 1.f / (1.f + expf(-iv));
                float sf = 1.f / (1.f + expf(-fv));
                float so = 1.f / (1.f + expf(-ov));
                float c_old = g_c[b3 * H_ + u];
                float c_new = sf * c_old + si * tanhf(gg);
                g_c[b3 * H_ + u]   = c_new;
                h_out[b3 * H_ + u] = so * tanhf(c_new);
            }
        }
        nb++; gbar_arrive_wait(nb * 256);

        // ---- Phase B: scores ----
        {
            const float* hn = g_h[(t + 1) & 1] + b2 * H_;
            for (int i = tid; i < H_; i += 256) hb_sh[i] = hn[i];
            __syncthreads();
            int s0 = j * 16 + warp * 2;
            const float* p0 = g_proj + ((size_t)b2 * S_ + s0) * H_;
            const float* p1 = p0 + H_;
            float a0 = 0.f, a1 = 0.f;
            #pragma unroll 4
            for (int k = lane; k < H_; k += 32) {
                float hv = hb_sh[k];
                a0 += hv * p0[k];
                a1 += hv * p1[k];
            }
            #pragma unroll
            for (int o = 16; o; o >>= 1) {
                a0 += __shfl_xor_sync(0xFFFFFFFFu, a0, o);
                a1 += __shfl_xor_sync(0xFFFFFFFFu, a1, o);
            }
            if (lane == 0) { g_sc[b2 * S_ + s0] = a0; g_sc[b2 * S_ + s0 + 1] = a1; }
        }
        nb++; gbar_arrive_wait(nb * 256);

        // ---- Phase C: softmax + ctx chunk ----
        {
            if (tid < S_) {
                float v = g_sc[b2 * S_ + tid];
                sc_sh[tid] = (tid < len) ? v : -1e9f;
            }
            __syncthreads();
            float m = (tid < S_) ? sc_sh[tid] : -1e30f;
            #pragma unroll
            for (int o = 16; o; o >>= 1) m = fmaxf(m, __shfl_xor_sync(0xFFFFFFFFu, m, o));
            if (lane == 0) red[warp] = m;
            __syncthreads();
            if (tid == 0) {
                float mm = red[0];
                for (int i = 1; i < 8; i++) mm = fmaxf(mm, red[i]);
                red[32] = mm;
            }
            __syncthreads();
            float mx = red[32];
            float p = (tid < S_) ? expf(sc_sh[tid] - mx) : 0.f;
            float ps = p;
            #pragma unroll
            for (int o = 16; o; o >>= 1) ps += __shfl_xor_sync(0xFFFFFFFFu, ps, o);
            if (lane == 0) red[warp] = ps;
            __syncthreads();
            if (tid == 0) {
                float sm = 0.f;
                for (int i = 0; i < 8; i++) sm += red[i];
                red[33] = 1.f / sm;
            }
            __syncthreads();
            if (tid < S_) sc_sh[tid] = p * red[33];
            __syncthreads();

            int cc = tid & 63, pq = tid >> 6;
            int e  = j * 64 + cc;
            const float* eb = enc + ((size_t)b2 * S_ + pq * 32) * ENC_ + e;
            float a = 0.f;
            #pragma unroll 8
            for (int s = 0; s < 32; s++) a += sc_sh[pq * 32 + s] * eb[(size_t)s * ENC_];
            part[pq][cc] = a;
            __syncthreads();
            if (tid < 64) {
                float cx = part[0][tid] + part[1][tid] + part[2][tid] + part[3][tid];
                float* dst = g_hcat + (size_t)(b2 * T_ + t) * (H_ + ENC_);
                dst[H_ + j * 64 + tid] = cx;
                dst[j * 64 + tid] = g_h[(t + 1) & 1][b2 * H_ + j * 64 + tid];
            }
        }
        nb++; gbar_arrive_wait(nb * 256);
    }
}

// ---------------- launch ----------------
extern "C" void kernel_launch(void* const* d_in, const int* in_sizes, int n_in,
                              void* d_out, int out_size) {
    const int*   gold   = (const int*)  d_in[0];
    const float* enc    = (const float*)d_in[1];
    const int*   lens   = (const int*)  d_in[2];
    const float* h0     = (const float*)d_in[3];
    const float* c0     = (const float*)d_in[4];
    const float* table  = (const float*)d_in[5];
    const float* W_ih   = (const float*)d_in[6];
    const float* W_hh   = (const float*)d_in[7];
    const float* b_ih   = (const float*)d_in[8];
    const float* b_hh   = (const float*)d_in[9];
    const float* Wa     = (const float*)d_in[10];
    const float* Wc_w   = (const float*)d_in[11];
    const float* Wc_b   = (const float*)d_in[12];
    const float* Wo_w   = (const float*)d_in[13];
    const float* Wo_b   = (const float*)d_in[14];
    float* out = (float*)d_out;

    float *p_emb, *p_X, *p_proj, *p_hcat, *p_ho, *p_bias;
    cudaGetSymbolAddress((void**)&p_emb,  g_emb);
    cudaGetSymbolAddress((void**)&p_X,    g_X);
    cudaGetSymbolAddress((void**)&p_proj, g_proj);
    cudaGetSymbolAddress((void**)&p_hcat, g_hcat);
    cudaGetSymbolAddress((void**)&p_ho,   g_ho);
    cudaGetSymbolAddress((void**)&p_bias, g_bias);
    __nv_bfloat16 *p_Abig, *p_Bbig;
    cudaGetSymbolAddress((void**)&p_Abig, g_Abig);
    cudaGetSymbolAddress((void**)&p_Bbig, g_Bbig);

    cudaFuncSetAttribute(k_hmma, cudaFuncAttributeMaxDynamicSharedMemorySize, HS_TOTAL);

    k_init<<<64, 256>>>(h0, c0, b_ih, b_hh);
    k_embed<<<BT_, 256>>>(gold, table);
    k_splitB<<<(V_*H_ + 255)/256, 256>>>(Wo_w);

    // X = emb @ W_ih^T + bias     [2048 x 2048, K=256]
    k_gemm<<<dim3(G4_/128, BT_/128), 256>>>(p_emb, W_ih, p_bias, p_X, BT_, G4_, E_);
    // proj_enc = enc @ Wa^T       [4096 x 512, K=512]
    k_gemm<<<dim3(H_/128, (B_*S_)/128), 256>>>(enc, Wa, nullptr, p_proj, B_*S_, H_, ENC_);

    // fused persistent decode loop
    k_loop<<<256, 256>>>(W_hh, enc, lens);

    // HO = [h;ctx] @ Wc_w^T + Wc_b   [2048 x 512, K=1024]
    k_gemm<<<dim3(H_/128, BT_/128), 256>>>(p_hcat, Wc_w, Wc_b, p_ho, BT_, H_, H_+ENC_);
    // split ho into K-concat bf16 operand
    k_splitA<<<(BT_*H_ + 255)/256, 256>>>(p_ho);
    // logits via mma.sync bf16 (error-compensated, K=1536), 128x256 tiles
    k_hmma<<<dim3(V_/256, BT_/128), 256, HS_TOTAL>>>(p_Abig, p_Bbig, Wo_b, out);
}

// round 12
// speedup vs baseline: 2.5274x; 1.2301x over previous
#include <cuda_runtime.h>
#include <cuda_bf16.h>
#include <cuda_fp16.h>
#include <math.h>
#include <stdint.h>

#define B_  32
#define T_  64
#define S_  128
#define E_  256
#define H_  512
#define ENC_ 512
#define V_  32000
#define G4_ (4*H_)   // 2048
#define BT_ (B_*T_)  // 2048
#define KBIG 1024    // 2 * H_ : [hoHi|hoHi] x [WoHi|WoLo]  (fp16 2-span)
#define NKIT 32      // KBIG / 32

// ---------------- scratch (static device globals; no allocation) ----------------
__device__ float g_emb [BT_*E_];
__device__ float g_X   [BT_*G4_];
__device__ float g_proj[B_*S_*H_];
__device__ float g_bias[G4_];
__device__ float g_h   [2][B_*H_];
__device__ float g_c   [B_*H_];
__device__ float g_hcat[BT_*(H_+ENC_)];
__device__ float g_ho  [BT_*H_];
__device__ float g_sc  [B_*S_];           // raw attention scores per step
__device__ unsigned g_bar;                // global barrier counter (reset by k_init)
// K-concatenated fp16 operands for the HMMA logits GEMM
__device__ __align__(128) __half g_Abig[BT_*KBIG];        // 4 MB
__device__ __align__(128) __half g_Bbig[(size_t)V_*KBIG]; // 65 MB

// ---------------- init ----------------
__global__ void k_init(const float* __restrict__ h0, const float* __restrict__ c0,
                       const float* __restrict__ b_ih, const float* __restrict__ b_hh) {
    int i = blockIdx.x * blockDim.x + threadIdx.x;
    if (i == 0) g_bar = 0u;
    if (i < B_*H_) { g_h[0][i] = h0[i]; g_c[i] = c0[i]; }
    if (i < G4_)   g_bias[i] = b_ih[i] + b_hh[i];
}

// ---------------- embedding gather ----------------
__global__ void k_embed(const int* __restrict__ tok, const float* __restrict__ table) {
    int bt = blockIdx.x;
    int e  = threadIdx.x;
    g_emb[bt*E_ + e] = table[tok[bt]*E_ + e];
}

// ---------------- fp32 -> fp16 splits into K-concat layouts ----------------
__global__ void k_splitA(const float* __restrict__ src) {   // ho [2048,512] -> [hi|hi]
    int i = blockIdx.x * blockDim.x + threadIdx.x;
    if (i < BT_*H_) {
        int row = i >> 9, k = i & 511;
        __half h = __float2half(src[i]);
        size_t b = (size_t)row * KBIG;
        g_Abig[b + k]       = h;
        g_Abig[b + 512 + k] = h;
    }
}
__global__ void k_splitB(const float* __restrict__ src) {   // Wo_w [32000,512] -> [hi|lo]
    int i = blockIdx.x * blockDim.x + threadIdx.x;
    if (i < V_*H_) {
        int row = i >> 9, k = i & 511;
        float a = src[i];
        __half h = __float2half(a);
        __half l = __float2half(a - __half2float(h));
        size_t b = (size_t)row * KBIG;
        g_Bbig[b + k]       = h;
        g_Bbig[b + 512 + k] = l;
    }
}

// ---------------- mma.sync helpers ----------------
__device__ __forceinline__ void ldsm_x4(uint32_t addr, uint32_t* r) {
    asm volatile("ldmatrix.sync.aligned.m8n8.x4.shared.b16 {%0,%1,%2,%3}, [%4];"
        : "=r"(r[0]), "=r"(r[1]), "=r"(r[2]), "=r"(r[3]) : "r"(addr));
}
__device__ __forceinline__ void mma16816(float* d, const uint32_t* a, const uint32_t* b) {
    asm volatile("mma.sync.aligned.m16n8k16.row.col.f32.f16.f16.f32 "
        "{%0,%1,%2,%3}, {%4,%5,%6,%7}, {%8,%9}, {%0,%1,%2,%3};"
        : "+f"(d[0]), "+f"(d[1]), "+f"(d[2]), "+f"(d[3])
        : "r"(a[0]), "r"(a[1]), "r"(a[2]), "r"(a[3]), "r"(b[0]), "r"(b[1]));
}
__device__ __forceinline__ void cp16(uint32_t dst, const void* src) {
    asm volatile("cp.async.cg.shared.global [%0], [%1], 16;" :: "r"(dst), "l"(src));
}
// conflict-free chunk swizzle: 64B rows of 4x16B chunks
#define SWZ(r, c) ((uint32_t)((r) * 64 + (((c) ^ (((r) >> 1) & 3)) << 4)))

// ---------------- HMMA logits GEMM (3-stage, 128x256 CTA, 64x64 warp) ----------
// C[2048, 32000] = A'[2048,1024] @ B'[32000,1024]^T + bias
#define HS_A 8192            // 128 rows x 64B per stage
#define HS_B 16384           // 256 rows x 64B per stage
#define HS_BOFF (3 * HS_A)
#define HS_TOTAL (3 * HS_A + 3 * HS_B)   // 73728

__global__ void __launch_bounds__(256, 1)
k_hmma(const __half* __restrict__ A, const __half* __restrict__ Bw,
       const float* __restrict__ bias, float* __restrict__ C) {
    extern __shared__ char hsm[];
    int tid = threadIdx.x, lane = tid & 31, warp = tid >> 5;
    int wm = warp >> 2, wn = warp & 3;          // 2 x 4 warp grid
    int bm = blockIdx.y * 128, bn = blockIdx.x * 256;
    uint32_t sb = (uint32_t)__cvta_generic_to_shared(hsm);

    float acc[4][8][4];
    #pragma unroll
    for (int i = 0; i < 4; i++)
        #pragma unroll
        for (int j = 0; j < 8; j++)
            #pragma unroll
            for (int v = 0; v < 4; v++) acc[i][j][v] = 0.f;

    auto load_stage = [&](int stage, int k0) {
        uint32_t sa = sb + stage * HS_A;
        uint32_t sbb = sb + HS_BOFF + stage * HS_B;
        #pragma unroll
        for (int i = 0; i < 2; i++) {
            int ch = tid + i * 256;
            int r = ch >> 2, c = ch & 3;
            cp16(sa + SWZ(r, c), &A[(size_t)(bm + r) * KBIG + k0 + c * 8]);
        }
        #pragma unroll
        for (int i = 0; i < 4; i++) {
            int ch = tid + i * 256;
            int r = ch >> 2, c = ch & 3;
            cp16(sbb + SWZ(r, c), &Bw[(size_t)(bn + r) * KBIG + k0 + c * 8]);
        }
        asm volatile("cp.async.commit_group;");
    };

    load_stage(0, 0);
    load_stage(1, 32);

    #pragma unroll 1
    for (int kt = 0; kt < NKIT; kt++) {
        if (kt == NKIT - 1) asm volatile("cp.async.wait_group 0;");
        else                asm volatile("cp.async.wait_group 1;");
        __syncthreads();

        if (kt + 2 < NKIT) load_stage((kt + 2) % 3, (kt + 2) * 32);

        int st = kt % 3;
        uint32_t abase = sb + st * HS_A;
        uint32_t bbase = sb + HS_BOFF + st * HS_B;
        #pragma unroll
        for (int kk = 0; kk < 2; kk++) {
            int kb = kk * 2;
            uint32_t a[4][4], b[4][4];
            #pragma unroll
            for (int i = 0; i < 4; i++) {
                int r = wm * 64 + i * 16 + (lane & 15);
                int c = kb + (lane >> 4);
                ldsm_x4(abase + SWZ(r, c), a[i]);
            }
            #pragma unroll
            for (int j = 0; j < 4; j++) {
                int r = wn * 64 + j * 16 + ((lane & 16) >> 1) + (lane & 7);
                int c = kb + ((lane >> 3) & 1);
                ldsm_x4(bbase + SWZ(r, c), b[j]);
            }
            #pragma unroll
            for (int i = 0; i < 4; i++)
                #pragma unroll
                for (int jn = 0; jn < 8; jn++)
                    mma16816(acc[i][jn], a[i], b[jn >> 1] + (jn & 1) * 2);
        }
        __syncthreads();
    }

    int g = lane >> 2, q = lane & 3;
    #pragma unroll
    for (int i = 0; i < 4; i++) {
        int rr = bm + wm * 64 + i * 16 + g;
        #pragma unroll
        for (int jn = 0; jn < 8; jn++) {
            int cb = bn + wn * 64 + jn * 8 + q * 2;
            float bb0 = bias[cb], bb1 = bias[cb + 1];
            C[(size_t)rr * V_ + cb]           = acc[i][jn][0] + bb0;
            C[(size_t)rr * V_ + cb + 1]       = acc[i][jn][1] + bb1;
            C[(size_t)(rr + 8) * V_ + cb]     = acc[i][jn][2] + bb0;
            C[(size_t)(rr + 8) * V_ + cb + 1] = acc[i][jn][3] + bb1;
        }
    }
}

// ---------------- generic SGEMM: C[M,N] = A[M,K] @ Bw[N,K]^T + bias ----------------
__global__ void __launch_bounds__(256)
k_gemm(const float* __restrict__ A, const float* __restrict__ Bw,
       const float* __restrict__ bias, float* __restrict__ C,
       int M, int N, int K) {
    __shared__ float As[16][128];
    __shared__ float Bs[16][128];
    int tid = threadIdx.x;
    int bm = blockIdx.y * 128, bn = blockIdx.x * 128;
    int tm = (tid >> 4) * 8;
    int tn = (tid & 15) * 8;
    float acc[8][8];
    #pragma unroll
    for (int i = 0; i < 8; i++)
        #pragma unroll
        for (int j = 0; j < 8; j++) acc[i][j] = 0.f;

    for (int k0 = 0; k0 < K; k0 += 16) {
        #pragma unroll
        for (int i = 0; i < 2; i++) {
            int f   = tid * 2 + i;
            int row = f >> 2;
            int col = (f & 3) * 4;
            float4 v = *(const float4*)&A[(size_t)(bm + row) * K + k0 + col];
            As[col+0][row] = v.x; As[col+1][row] = v.y;
            As[col+2][row] = v.z; As[col+3][row] = v.w;
        }
        #pragma unroll
        for (int i = 0; i < 2; i++) {
            int f   = tid * 2 + i;
            int row = f >> 2;
            int col = (f & 3) * 4;
            float4 v = *(const float4*)&Bw[(size_t)(bn + row) * K + k0 + col];
            Bs[col+0][row] = v.x; Bs[col+1][row] = v.y;
            Bs[col+2][row] = v.z; Bs[col+3][row] = v.w;
        }
        __syncthreads();
        #pragma unroll
        for (int k = 0; k < 16; k++) {
            float a[8], b[8];
            float4 a0 = *(const float4*)&As[k][tm];
            float4 a1 = *(const float4*)&As[k][tm+4];
            float4 b0 = *(const float4*)&Bs[k][tn];
            float4 b1 = *(const float4*)&Bs[k][tn+4];
            a[0]=a0.x; a[1]=a0.y; a[2]=a0.z; a[3]=a0.w;
            a[4]=a1.x; a[5]=a1.y; a[6]=a1.z; a[7]=a1.w;
            b[0]=b0.x; b[1]=b0.y; b[2]=b0.z; b[3]=b0.w;
            b[4]=b1.x; b[5]=b1.y; b[6]=b1.z; b[7]=b1.w;
            #pragma unroll
            for (int i = 0; i < 8; i++)
                #pragma unroll
                for (int j = 0; j < 8; j++)
                    acc[i][j] += a[i] * b[j];
        }
        __syncthreads();
    }
    #pragma unroll
    for (int i = 0; i < 8; i++) {
        #pragma unroll
        for (int j = 0; j < 8; j++) {
            float v = acc[i][j];
            if (bias) v += bias[bn + tn + j];
            C[(size_t)(bm + tm + i) * N + bn + tn + j] = v;
        }
    }
}

// ---------------- persistent fused decode loop (2 barriers/step) ----------------
__device__ __forceinline__ void gbar_arrive_wait(unsigned target) {
    __syncthreads();
    if (threadIdx.x == 0) {
        __threadfence();
        atomicAdd(&g_bar, 1u);
        for (int i = 0; i < (1 << 22); i++) {
            if (*(volatile unsigned*)&g_bar >= target) break;
        }
        __threadfence();
    }
    __syncthreads();
}

__global__ void __launch_bounds__(256, 2)
k_loop(const float* __restrict__ W_hh, const float* __restrict__ enc,
       const int* __restrict__ lens) {
    __shared__ float w_sh[8][H_];        // 16 KB : this CTA's 8 W_hh rows
    __shared__ float apart[8][8][33];    // 8.4 KB: phase-A partials [slice][r][b]
    __shared__ float sg[8][33];
    __shared__ float hb_sh[H_];
    __shared__ float sc_sh[S_];
    __shared__ float red[34];
    __shared__ float cpart[4][64];
    int tid = threadIdx.x;
    int bid = blockIdx.x;
    int ub  = bid * 2;
    int warp = tid >> 5, lane = tid & 31;

    for (int rr = 0; rr < 8; rr++) {
        int row = (rr & 3) * H_ + ub + (rr >> 2);
        for (int k = tid; k < H_; k += 256)
            w_sh[rr][k] = W_hh[(size_t)row * H_ + k];
    }
    __syncthreads();

    int b2 = bid >> 3, j = bid & 7;
    int len = lens[b2];
    unsigned nb = 0;

    for (int t = 0; t < T_; t++) {
        // ---- Phase A: gates + LSTM pointwise ----
        // thread (b=lane, slice=warp): 8 reg accumulators over this CTA's 8 rows,
        // h read once per thread (float4 LDG), w via broadcast LDS.128.
        {
            const float* h_in  = g_h[t & 1];
            float*       h_out = g_h[(t + 1) & 1];
            float acc[8];
            #pragma unroll
            for (int r = 0; r < 8; r++) acc[r] = 0.f;
            const float4* hp = (const float4*)(h_in + lane * H_ + warp * 64);
            #pragma unroll
            for (int k4 = 0; k4 < 16; k4++) {
                float4 hv = hp[k4];
                #pragma unroll
                for (int r = 0; r < 8; r++) {
                    float4 wv = *(const float4*)&w_sh[r][warp * 64 + k4 * 4];
                    acc[r] += hv.x*wv.x + hv.y*wv.y + hv.z*wv.z + hv.w*wv.w;
                }
            }
            #pragma unroll
            for (int r = 0; r < 8; r++) apart[warp][r][lane] = acc[r];
            __syncthreads();
            {   // reduce 8 slices: thread (r=warp, b=lane)
                float gv = 0.f;
                #pragma unroll
                for (int s = 0; s < 8; s++) gv += apart[s][warp][lane];
                int row = (warp & 3) * H_ + ub + (warp >> 2);
                gv += g_X[(size_t)(lane * T_ + t) * G4_ + row];
                sg[warp][lane] = gv;
            }
            __syncthreads();
            if (tid < 64) {
                int q2 = tid >> 5, b3 = tid & 31;
                int u  = ub + q2;
                float iv = sg[q2*4 + 0][b3];
                float fv = sg[q2*4 + 1][b3];
                float gg = sg[q2*4 + 2][b3];
                float ov = sg[q2*4 + 3][b3];
                float si = 1.f / (1.f + expf(-iv));
                float sf = 1.f / (1.f + expf(-fv));
                float so = 1.f / (1.f + expf(-ov));
                float c_old = g_c[b3 * H_ + u];
                float c_new = sf * c_old + si * tanhf(gg);
                g_c[b3 * H_ + u]   = c_new;
                h_out[b3 * H_ + u] = so * tanhf(c_new);
            }
        }
        nb++; gbar_arrive_wait(nb * 256);

        // ---- Phase B: scores for s in [j*16, j*16+16) of batch b2 ----
        {
            const float* hn = g_h[(t + 1) & 1] + b2 * H_;
            for (int i = tid; i < H_; i += 256) hb_sh[i] = hn[i];
            __syncthreads();
            int s0 = j * 16 + warp * 2;
            const float* p0 = g_proj + ((size_t)b2 * S_ + s0) * H_;
            const float* p1 = p0 + H_;
            float a0 = 0.f, a1 = 0.f;
            #pragma unroll 4
            for (int k = lane; k < H_; k += 32) {
                float hv = hb_sh[k];
                a0 += hv * p0[k];
                a1 += hv * p1[k];
            }
            #pragma unroll
            for (int o = 16; o; o >>= 1) {
                a0 += __shfl_xor_sync(0xFFFFFFFFu, a0, o);
                a1 += __shfl_xor_sync(0xFFFFFFFFu, a1, o);
            }
            if (lane == 0) { g_sc[b2 * S_ + s0] = a0; g_sc[b2 * S_ + s0 + 1] = a1; }
        }
        nb++; gbar_arrive_wait(nb * 256);

        // ---- Phase C: softmax + ctx chunk (pure sink; no trailing barrier) ----
        {
            if (tid < S_) {
                float v = g_sc[b2 * S_ + tid];
                sc_sh[tid] = (tid < len) ? v : -1e9f;
            }
            __syncthreads();
            float m = (tid < S_) ? sc_sh[tid] : -1e30f;
            #pragma unroll
            for (int o = 16; o; o >>= 1) m = fmaxf(m, __shfl_xor_sync(0xFFFFFFFFu, m, o));
            if (lane == 0) red[warp] = m;
            __syncthreads();
            if (tid == 0) {
                float mm = red[0];
                for (int i = 1; i < 8; i++) mm = fmaxf(mm, red[i]);
                red[32] = mm;
            }
            __syncthreads();
            float mx = red[32];
            float p = (tid < S_) ? expf(sc_sh[tid] - mx) : 0.f;
            float ps = p;
            #pragma unroll
            for (int o = 16; o; o >>= 1) ps += __shfl_xor_sync(0xFFFFFFFFu, ps, o);
            if (lane == 0) red[warp] = ps;
            __syncthreads();
            if (tid == 0) {
                float sm = 0.f;
                for (int i = 0; i < 8; i++) sm += red[i];
                red[33] = 1.f / sm;
            }
            __syncthreads();
            if (tid < S_) sc_sh[tid] = p * red[33];
            __syncthreads();

            int cc = tid & 63, pq = tid >> 6;
            int e  = j * 64 + cc;
            const float* eb = enc + ((size_t)b2 * S_ + pq * 32) * ENC_ + e;
            float a = 0.f;
            #pragma unroll 8
            for (int s = 0; s < 32; s++) a += sc_sh[pq * 32 + s] * eb[(size_t)s * ENC_];
            cpart[pq][cc] = a;
            __syncthreads();
            if (tid < 64) {
                float cx = cpart[0][tid] + cpart[1][tid] + cpart[2][tid] + cpart[3][tid];
                float* dst = g_hcat + (size_t)(b2 * T_ + t) * (H_ + ENC_);
                dst[H_ + j * 64 + tid] = cx;
                dst[j * 64 + tid] = g_h[(t + 1) & 1][b2 * H_ + j * 64 + tid];
            }
            __syncthreads();
        }
    }
}

// ---------------- launch ----------------
extern "C" void kernel_launch(void* const* d_in, const int* in_sizes, int n_in,
                              void* d_out, int out_size) {
    const int*   gold   = (const int*)  d_in[0];
    const float* enc    = (const float*)d_in[1];
    const int*   lens   = (const int*)  d_in[2];
    const float* h0     = (const float*)d_in[3];
    const float* c0     = (const float*)d_in[4];
    const float* table  = (const float*)d_in[5];
    const float* W_ih   = (const float*)d_in[6];
    const float* W_hh   = (const float*)d_in[7];
    const float* b_ih   = (const float*)d_in[8];
    const float* b_hh   = (const float*)d_in[9];
    const float* Wa     = (const float*)d_in[10];
    const float* Wc_w   = (const float*)d_in[11];
    const float* Wc_b   = (const float*)d_in[12];
    const float* Wo_w   = (const float*)d_in[13];
    const float* Wo_b   = (const float*)d_in[14];
    float* out = (float*)d_out;

    float *p_emb, *p_X, *p_proj, *p_hcat, *p_ho, *p_bias;
    cudaGetSymbolAddress((void**)&p_emb,  g_emb);
    cudaGetSymbolAddress((void**)&p_X,    g_X);
    cudaGetSymbolAddress((void**)&p_proj, g_proj);
    cudaGetSymbolAddress((void**)&p_hcat, g_hcat);
    cudaGetSymbolAddress((void**)&p_ho,   g_ho);
    cudaGetSymbolAddress((void**)&p_bias, g_bias);
    __half *p_Abig, *p_Bbig;
    cudaGetSymbolAddress((void**)&p_Abig, g_Abig);
    cudaGetSymbolAddress((void**)&p_Bbig, g_Bbig);

    cudaFuncSetAttribute(k_hmma, cudaFuncAttributeMaxDynamicSharedMemorySize, HS_TOTAL);

    k_init<<<64, 256>>>(h0, c0, b_ih, b_hh);
    k_embed<<<BT_, 256>>>(gold, table);
    k_splitB<<<(V_*H_ + 255)/256, 256>>>(Wo_w);

    // X = emb @ W_ih^T + bias     [2048 x 2048, K=256]
    k_gemm<<<dim3(G4_/128, BT_/128), 256>>>(p_emb, W_ih, p_bias, p_X, BT_, G4_, E_);
    // proj_enc = enc @ Wa^T       [4096 x 512, K=512]
    k_gemm<<<dim3(H_/128, (B_*S_)/128), 256>>>(enc, Wa, nullptr, p_proj, B_*S_, H_, ENC_);

    // fused persistent decode loop
    k_loop<<<256, 256>>>(W_hh, enc, lens);

    // HO = [h;ctx] @ Wc_w^T + Wc_b   [2048 x 512, K=1024]
    k_gemm<<<dim3(H_/128, BT_/128), 256>>>(p_hcat, Wc_w, Wc_b, p_ho, BT_, H_, H_+ENC_);
    // split ho into K-concat fp16 operand
    k_splitA<<<(BT_*H_ + 255)/256, 256>>>(p_ho);
    // logits via mma.sync fp16 (2-span error-compensated, K=1024), 128x256 tiles
    k_hmma<<<dim3(V_/256, BT_/128), 256, HS_TOTAL>>>(p_Abig, p_Bbig, Wo_b, out);
}

// round 14
// speedup vs baseline: 3.0559x; 1.2091x over previous
#include <cuda_runtime.h>
#include <cuda_bf16.h>
#include <cuda_fp16.h>
#include <math.h>
#include <stdint.h>

#define B_  32
#define T_  64
#define S_  128
#define E_  256
#define H_  512
#define ENC_ 512
#define V_  32000
#define G4_ (4*H_)   // 2048
#define BT_ (B_*T_)  // 2048

// ---------------- scratch (static device globals; no allocation) ----------------
__device__ float g_emb [BT_*E_];
__device__ float g_X   [BT_*G4_];
__device__ float g_proj[B_*S_*H_];
__device__ float g_bias[G4_];
__device__ float g_h   [2][B_*H_];
__device__ float g_c   [B_*H_];
__device__ float g_hcat[BT_*(H_+ENC_)];
__device__ float g_ho  [BT_*H_];
__device__ float g_sc  [B_*S_];
__device__ unsigned g_bar;
// fp16 operands for the four HMMA GEMMs
__device__ __align__(128) __half gX_A[BT_*3*E_];          // emb 3-span [hi|hi|lo]
__device__ __align__(128) __half gX_B[G4_*3*E_];          // W_ih 3-span [hi|lo|hi]
__device__ __align__(128) __half gP_A[B_*S_*3*ENC_];      // enc 3-span
__device__ __align__(128) __half gP_B[H_*3*ENC_];         // Wa 3-span
__device__ __align__(128) __half gW_A[BT_*2*(H_+ENC_)];   // hcat 2-span [hi|hi]
__device__ __align__(128) __half gW_B[H_*2*(H_+ENC_)];    // Wc 2-span [hi|lo]
__device__ __align__(128) __half gL_A[BT_*H_];            // ho single-span
__device__ __align__(128) __half gL_B[(size_t)V_*H_];     // Wo single-span

// ---------------- init ----------------
__global__ void k_init(const float* __restrict__ h0, const float* __restrict__ c0,
                       const float* __restrict__ b_ih, const float* __restrict__ b_hh) {
    int i = blockIdx.x * blockDim.x + threadIdx.x;
    if (i == 0) g_bar = 0u;
    if (i < B_*H_) { g_h[0][i] = h0[i]; g_c[i] = c0[i]; }
    if (i < G4_)   g_bias[i] = b_ih[i] + b_hh[i];
}

// ---------------- embedding gather ----------------
__global__ void k_embed(const int* __restrict__ tok, const float* __restrict__ table) {
    int bt = blockIdx.x;
    int e  = threadIdx.x;
    g_emb[bt*E_ + e] = table[tok[bt]*E_ + e];
}

// ---------------- fp32 -> fp16 span split ----------------
// pattern bit s: 0 = hi span, 1 = lo span. K-concat layout [span0|span1|...].
__global__ void k_split(const float* __restrict__ src, __half* __restrict__ dst,
                        int total, int kshift, int nspans, int pattern) {
    int i = blockIdx.x * blockDim.x + threadIdx.x;
    if (i >= total) return;
    int kdim = 1 << kshift;
    int row = i >> kshift, k = i & (kdim - 1);
    float a = src[i];
    __half h = __float2half(a);
    __half l = __float2half(a - __half2float(h));
    size_t base = (size_t)row * ((size_t)nspans << kshift) + k;
    for (int s = 0; s < nspans; s++)
        dst[base + ((size_t)s << kshift)] = ((pattern >> s) & 1) ? l : h;
}

// ---------------- mma.sync helpers ----------------
__device__ __forceinline__ void ldsm_x4(uint32_t addr, uint32_t* r) {
    asm volatile("ldmatrix.sync.aligned.m8n8.x4.shared.b16 {%0,%1,%2,%3}, [%4];"
        : "=r"(r[0]), "=r"(r[1]), "=r"(r[2]), "=r"(r[3]) : "r"(addr));
}
__device__ __forceinline__ void mma16816(float* d, const uint32_t* a, const uint32_t* b) {
    asm volatile("mma.sync.aligned.m16n8k16.row.col.f32.f16.f16.f32 "
        "{%0,%1,%2,%3}, {%4,%5,%6,%7}, {%8,%9}, {%0,%1,%2,%3};"
        : "+f"(d[0]), "+f"(d[1]), "+f"(d[2]), "+f"(d[3])
        : "r"(a[0]), "r"(a[1]), "r"(a[2]), "r"(a[3]), "r"(b[0]), "r"(b[1]));
}
__device__ __forceinline__ void cp16(uint32_t dst, const void* src) {
    asm volatile("cp.async.cg.shared.global [%0], [%1], 16;" :: "r"(dst), "l"(src));
}
#define SWZ(r, c) ((uint32_t)((r) * 64 + (((c) ^ (((r) >> 1) & 3)) << 4)))

// ---------------- unified HMMA GEMM (3-stage, 128x256 CTA, 64x64 warp) ----------
// C[M,N] = A'[M,K] @ B'[N,K]^T (+ bias). K runtime, divisible by 32, K/32 >= 2.
#define HS_A 8192
#define HS_B 16384
#define HS_BOFF (3 * HS_A)
#define HS_TOTAL (3 * HS_A + 3 * HS_B)   // 73728

__global__ void __launch_bounds__(256, 1)
k_hmma(const __half* __restrict__ A, const __half* __restrict__ Bw,
       const float* __restrict__ bias, float* __restrict__ C, int K, int N) {
    extern __shared__ char hsm[];
    int tid = threadIdx.x, lane = tid & 31, warp = tid >> 5;
    int wm = warp >> 2, wn = warp & 3;
    int bm = blockIdx.y * 128, bn = blockIdx.x * 256;
    uint32_t sb = (uint32_t)__cvta_generic_to_shared(hsm);
    int nkit = K >> 5;

    float acc[4][8][4];
    #pragma unroll
    for (int i = 0; i < 4; i++)
        #pragma unroll
        for (int j = 0; j < 8; j++)
            #pragma unroll
            for (int v = 0; v < 4; v++) acc[i][j][v] = 0.f;

    auto load_stage = [&](int stage, int k0) {
        uint32_t sa = sb + stage * HS_A;
        uint32_t sbb = sb + HS_BOFF + stage * HS_B;
        #pragma unroll
        for (int i = 0; i < 2; i++) {
            int ch = tid + i * 256;
            int r = ch >> 2, c = ch & 3;
            cp16(sa + SWZ(r, c), &A[(size_t)(bm + r) * K + k0 + c * 8]);
        }
        #pragma unroll
        for (int i = 0; i < 4; i++) {
            int ch = tid + i * 256;
            int r = ch >> 2, c = ch & 3;
            cp16(sbb + SWZ(r, c), &Bw[(size_t)(bn + r) * K + k0 + c * 8]);
        }
        asm volatile("cp.async.commit_group;");
    };

    load_stage(0, 0);
    load_stage(1, 32);

    #pragma unroll 1
    for (int kt = 0; kt < nkit; kt++) {
        if (kt == nkit - 1) asm volatile("cp.async.wait_group 0;");
        else                asm volatile("cp.async.wait_group 1;");
        __syncthreads();

        if (kt + 2 < nkit) load_stage((kt + 2) % 3, (kt + 2) * 32);

        int st = kt % 3;
        uint32_t abase = sb + st * HS_A;
        uint32_t bbase = sb + HS_BOFF + st * HS_B;
        #pragma unroll
        for (int kk = 0; kk < 2; kk++) {
            int kb = kk * 2;
            uint32_t a[4][4], b[4][4];
            #pragma unroll
            for (int i = 0; i < 4; i++) {
                int r = wm * 64 + i * 16 + (lane & 15);
                int c = kb + (lane >> 4);
                ldsm_x4(abase + SWZ(r, c), a[i]);
            }
            #pragma unroll
            for (int j = 0; j < 4; j++) {
                int r = wn * 64 + j * 16 + ((lane & 16) >> 1) + (lane & 7);
                int c = kb + ((lane >> 3) & 1);
                ldsm_x4(bbase + SWZ(r, c), b[j]);
            }
            #pragma unroll
            for (int i = 0; i < 4; i++)
                #pragma unroll
                for (int jn = 0; jn < 8; jn++)
                    mma16816(acc[i][jn], a[i], b[jn >> 1] + (jn & 1) * 2);
        }
        __syncthreads();
    }

    int g = lane >> 2, q = lane & 3;
    #pragma unroll
    for (int i = 0; i < 4; i++) {
        int rr = bm + wm * 64 + i * 16 + g;
        #pragma unroll
        for (int jn = 0; jn < 8; jn++) {
            int cb = bn + wn * 64 + jn * 8 + q * 2;
            float bb0 = bias ? bias[cb] : 0.f;
            float bb1 = bias ? bias[cb + 1] : 0.f;
            C[(size_t)rr * N + cb]           = acc[i][jn][0] + bb0;
            C[(size_t)rr * N + cb + 1]       = acc[i][jn][1] + bb1;
            C[(size_t)(rr + 8) * N + cb]     = acc[i][jn][2] + bb0;
            C[(size_t)(rr + 8) * N + cb + 1] = acc[i][jn][3] + bb1;
        }
    }
}

// ---------------- persistent fused decode loop (unchanged from R12) ----------------
__device__ __forceinline__ void gbar_arrive_wait(unsigned target) {
    __syncthreads();
    if (threadIdx.x == 0) {
        __threadfence();
        atomicAdd(&g_bar, 1u);
        for (int i = 0; i < (1 << 22); i++) {
            if (*(volatile unsigned*)&g_bar >= target) break;
        }
        __threadfence();
    }
    __syncthreads();
}

__global__ void __launch_bounds__(256, 2)
k_loop(const float* __restrict__ W_hh, const float* __restrict__ enc,
       const int* __restrict__ lens) {
    __shared__ float w_sh[8][H_];
    __shared__ float apart[8][8][33];
    __shared__ float sg[8][33];
    __shared__ float hb_sh[H_];
    __shared__ float sc_sh[S_];
    __shared__ float red[34];
    __shared__ float cpart[4][64];
    int tid = threadIdx.x;
    int bid = blockIdx.x;
    int ub  = bid * 2;
    int warp = tid >> 5, lane = tid & 31;

    for (int rr = 0; rr < 8; rr++) {
        int row = (rr & 3) * H_ + ub + (rr >> 2);
        for (int k = tid; k < H_; k += 256)
            w_sh[rr][k] = W_hh[(size_t)row * H_ + k];
    }
    __syncthreads();

    int b2 = bid >> 3, j = bid & 7;
    int len = lens[b2];
    unsigned nb = 0;

    for (int t = 0; t < T_; t++) {
        // ---- Phase A: gates + LSTM pointwise ----
        {
            const float* h_in  = g_h[t & 1];
            float*       h_out = g_h[(t + 1) & 1];
            float acc[8];
            #pragma unroll
            for (int r = 0; r < 8; r++) acc[r] = 0.f;
            const float4* hp = (const float4*)(h_in + lane * H_ + warp * 64);
            #pragma unroll
            for (int k4 = 0; k4 < 16; k4++) {
                float4 hv = hp[k4];
                #pragma unroll
                for (int r = 0; r < 8; r++) {
                    float4 wv = *(const float4*)&w_sh[r][warp * 64 + k4 * 4];
                    acc[r] += hv.x*wv.x + hv.y*wv.y + hv.z*wv.z + hv.w*wv.w;
                }
            }
            #pragma unroll
            for (int r = 0; r < 8; r++) apart[warp][r][lane] = acc[r];
            __syncthreads();
            {
                float gv = 0.f;
                #pragma unroll
                for (int s = 0; s < 8; s++) gv += apart[s][warp][lane];
                int row = (warp & 3) * H_ + ub + (warp >> 2);
                gv += g_X[(size_t)(lane * T_ + t) * G4_ + row];
                sg[warp][lane] = gv;
            }
            __syncthreads();
            if (tid < 64) {
                int q2 = tid >> 5, b3 = tid & 31;
                int u  = ub + q2;
                float iv = sg[q2*4 + 0][b3];
                float fv = sg[q2*4 + 1][b3];
                float gg = sg[q2*4 + 2][b3];
                float ov = sg[q2*4 + 3][b3];
                float si = 1.f / (1.f + expf(-iv));
                float sf = 1.f / (1.f + expf(-fv));
                float so = 1.f / (1.f + expf(-ov));
                float c_old = g_c[b3 * H_ + u];
                float c_new = sf * c_old + si * tanhf(gg);
                g_c[b3 * H_ + u]   = c_new;
                h_out[b3 * H_ + u] = so * tanhf(c_new);
            }
        }
        nb++; gbar_arrive_wait(nb * 256);

        // ---- Phase B: scores ----
        {
            const float* hn = g_h[(t + 1) & 1] + b2 * H_;
            for (int i = tid; i < H_; i += 256) hb_sh[i] = hn[i];
            __syncthreads();
            int s0 = j * 16 + warp * 2;
            const float* p0 = g_proj + ((size_t)b2 * S_ + s0) * H_;
            const float* p1 = p0 + H_;
            float a0 = 0.f, a1 = 0.f;
            #pragma unroll 4
            for (int k = lane; k < H_; k += 32) {
                float hv = hb_sh[k];
                a0 += hv * p0[k];
                a1 += hv * p1[k];
            }
            #pragma unroll
            for (int o = 16; o; o >>= 1) {
                a0 += __shfl_xor_sync(0xFFFFFFFFu, a0, o);
                a1 += __shfl_xor_sync(0xFFFFFFFFu, a1, o);
            }
            if (lane == 0) { g_sc[b2 * S_ + s0] = a0; g_sc[b2 * S_ + s0 + 1] = a1; }
        }
        nb++; gbar_arrive_wait(nb * 256);

        // ---- Phase C: softmax + ctx chunk ----
        {
            if (tid < S_) {
                float v = g_sc[b2 * S_ + tid];
                sc_sh[tid] = (tid < len) ? v : -1e9f;
            }
            __syncthreads();
            float m = (tid < S_) ? sc_sh[tid] : -1e30f;
            #pragma unroll
            for (int o = 16; o; o >>= 1) m = fmaxf(m, __shfl_xor_sync(0xFFFFFFFFu, m, o));
            if (lane == 0) red[warp] = m;
            __syncthreads();
            if (tid == 0) {
                float mm = red[0];
                for (int i = 1; i < 8; i++) mm = fmaxf(mm, red[i]);
                red[32] = mm;
            }
            __syncthreads();
            float mx = red[32];
            float p = (tid < S_) ? expf(sc_sh[tid] - mx) : 0.f;
            float ps = p;
            #pragma unroll
            for (int o = 16; o; o >>= 1) ps += __shfl_xor_sync(0xFFFFFFFFu, ps, o);
            if (lane == 0) red[warp] = ps;
            __syncthreads();
            if (tid == 0) {
                float sm = 0.f;
                for (int i = 0; i < 8; i++) sm += red[i];
                red[33] = 1.f / sm;
            }
            __syncthreads();
            if (tid < S_) sc_sh[tid] = p * red[33];
            __syncthreads();

            int cc = tid & 63, pq = tid >> 6;
            int e  = j * 64 + cc;
            const float* eb = enc + ((size_t)b2 * S_ + pq * 32) * ENC_ + e;
            float a = 0.f;
            #pragma unroll 8
            for (int s = 0; s < 32; s++) a += sc_sh[pq * 32 + s] * eb[(size_t)s * ENC_];
            cpart[pq][cc] = a;
            __syncthreads();
            if (tid < 64) {
                float cx = cpart[0][tid] + cpart[1][tid] + cpart[2][tid] + cpart[3][tid];
                float* dst = g_hcat + (size_t)(b2 * T_ + t) * (H_ + ENC_);
                dst[H_ + j * 64 + tid] = cx;
                dst[j * 64 + tid] = g_h[(t + 1) & 1][b2 * H_ + j * 64 + tid];
            }
            __syncthreads();
        }
    }
}

// ---------------- launch ----------------
extern "C" void kernel_launch(void* const* d_in, const int* in_sizes, int n_in,
                              void* d_out, int out_size) {
    const int*   gold   = (const int*)  d_in[0];
    const float* enc    = (const float*)d_in[1];
    const int*   lens   = (const int*)  d_in[2];
    const float* h0     = (const float*)d_in[3];
    const float* c0     = (const float*)d_in[4];
    const float* table  = (const float*)d_in[5];
    const float* W_ih   = (const float*)d_in[6];
    const float* W_hh   = (const float*)d_in[7];
    const float* b_ih   = (const float*)d_in[8];
    const float* b_hh   = (const float*)d_in[9];
    const float* Wa     = (const float*)d_in[10];
    const float* Wc_w   = (const float*)d_in[11];
    const float* Wc_b   = (const float*)d_in[12];
    const float* Wo_w   = (const float*)d_in[13];
    const float* Wo_b   = (const float*)d_in[14];
    float* out = (float*)d_out;

    float *p_emb, *p_X, *p_proj, *p_hcat, *p_ho, *p_bias;
    cudaGetSymbolAddress((void**)&p_emb,  g_emb);
    cudaGetSymbolAddress((void**)&p_X,    g_X);
    cudaGetSymbolAddress((void**)&p_proj, g_proj);
    cudaGetSymbolAddress((void**)&p_hcat, g_hcat);
    cudaGetSymbolAddress((void**)&p_ho,   g_ho);
    cudaGetSymbolAddress((void**)&p_bias, g_bias);
    __half *pX_A, *pX_B, *pP_A, *pP_B, *pW_A, *pW_B, *pL_A, *pL_B;
    cudaGetSymbolAddress((void**)&pX_A, gX_A);
    cudaGetSymbolAddress((void**)&pX_B, gX_B);
    cudaGetSymbolAddress((void**)&pP_A, gP_A);
    cudaGetSymbolAddress((void**)&pP_B, gP_B);
    cudaGetSymbolAddress((void**)&pW_A, gW_A);
    cudaGetSymbolAddress((void**)&pW_B, gW_B);
    cudaGetSymbolAddress((void**)&pL_A, gL_A);
    cudaGetSymbolAddress((void**)&pL_B, gL_B);

    cudaFuncSetAttribute(k_hmma, cudaFuncAttributeMaxDynamicSharedMemorySize, HS_TOTAL);

    k_init<<<64, 256>>>(h0, c0, b_ih, b_hh);
    k_embed<<<BT_, 256>>>(gold, table);

    // input splits (independent of the loop)
    k_split<<<(G4_*E_ + 255)/256, 256>>>(W_ih, pX_B, G4_*E_, 8, 3, 0b010);
    k_split<<<(B_*S_*ENC_ + 255)/256, 256>>>(enc, pP_A, B_*S_*ENC_, 9, 3, 0b100);
    k_split<<<(H_*ENC_ + 255)/256, 256>>>(Wa, pP_B, H_*ENC_, 9, 3, 0b010);
    k_split<<<(V_*H_ + 255)/256, 256>>>(Wo_w, pL_B, V_*H_, 9, 1, 0);
    k_split<<<(H_*(H_+ENC_) + 255)/256, 256>>>(Wc_w, pW_B, H_*(H_+ENC_), 10, 2, 0b10);
    k_split<<<(BT_*E_ + 255)/256, 256>>>(p_emb, pX_A, BT_*E_, 8, 3, 0b100);

    // X = emb @ W_ih^T + bias   (3-span fp16, K=768)
    k_hmma<<<dim3(G4_/256, BT_/128), 256, HS_TOTAL>>>(pX_A, pX_B, p_bias, p_X, 3*E_, G4_);
    // proj = enc @ Wa^T         (3-span fp16, K=1536)
    k_hmma<<<dim3(H_/256, (B_*S_)/128), 256, HS_TOTAL>>>(pP_A, pP_B, nullptr, p_proj, 3*ENC_, H_);

    // fused persistent decode loop
    k_loop<<<256, 256>>>(W_hh, enc, lens);

    // HO = [h;ctx] @ Wc_w^T + Wc_b  (2-span fp16, K=2048)
    k_split<<<(BT_*(H_+ENC_) + 255)/256, 256>>>(p_hcat, pW_A, BT_*(H_+ENC_), 10, 2, 0b00);
    k_hmma<<<dim3(H_/256, BT_/128), 256, HS_TOTAL>>>(pW_A, pW_B, Wc_b, p_ho, 2*(H_+ENC_), H_);

    // logits = ho @ Wo^T + Wo_b  (single-span fp16, K=512)
    k_split<<<(BT_*H_ + 255)/256, 256>>>(p_ho, pL_A, BT_*H_, 9, 1, 0);
    k_hmma<<<dim3(V_/256, BT_/128), 256, HS_TOTAL>>>(pL_A, pL_B, Wo_b, out, H_, V_);
}

// round 16
// speedup vs baseline: 3.1168x; 1.0199x over previous
#include <cuda_runtime.h>
#include <cuda_bf16.h>
#include <cuda_fp16.h>
#include <math.h>
#include <stdint.h>

#define B_  32
#define T_  64
#define S_  128
#define E_  256
#define H_  512
#define ENC_ 512
#define V_  32000
#define G4_ (4*H_)   // 2048
#define BT_ (B_*T_)  // 2048

// ---------------- scratch (static device globals; no allocation) ----------------
__device__ float g_emb [BT_*E_];
__device__ float g_X   [BT_*G4_];
__device__ float g_proj[B_*S_*H_];
__device__ float g_bias[G4_];
__device__ float g_h   [2][B_*H_];
__device__ float g_c   [B_*H_];
__device__ float g_hcat[BT_*(H_+ENC_)];
__device__ float g_ho  [BT_*H_];
__device__ float g_sc  [B_*S_];
__device__ unsigned g_bar;
__device__ unsigned g_cnt[B_*32];      // per-batch sub-barrier counters, 128B strided
// fp16 operands for the four HMMA GEMMs
__device__ __align__(128) __half gX_A[BT_*3*E_];          // emb 3-span [hi|hi|lo]
__device__ __align__(128) __half gX_B[G4_*3*E_];          // W_ih 3-span [hi|lo|hi]
__device__ __align__(128) __half gP_A[B_*S_*3*ENC_];      // enc 3-span
__device__ __align__(128) __half gP_B[H_*3*ENC_];         // Wa 3-span
__device__ __align__(128) __half gW_A[BT_*2*(H_+ENC_)];   // hcat 2-span [hi|hi]
__device__ __align__(128) __half gW_B[H_*2*(H_+ENC_)];    // Wc 2-span [hi|lo]
__device__ __align__(128) __half gL_A[BT_*H_];            // ho single-span
__device__ __align__(128) __half gL_B[(size_t)V_*H_];     // Wo single-span

// ---------------- init ----------------
__global__ void k_init(const float* __restrict__ h0, const float* __restrict__ c0,
                       const float* __restrict__ b_ih, const float* __restrict__ b_hh) {
    int i = blockIdx.x * blockDim.x + threadIdx.x;
    if (i == 0) g_bar = 0u;
    if (i < B_*32) g_cnt[i] = 0u;
    if (i < B_*H_) { g_h[0][i] = h0[i]; g_c[i] = c0[i]; }
    if (i < G4_)   g_bias[i] = b_ih[i] + b_hh[i];
}

// ---------------- embedding gather ----------------
__global__ void k_embed(const int* __restrict__ tok, const float* __restrict__ table) {
    int bt = blockIdx.x;
    int e  = threadIdx.x;
    g_emb[bt*E_ + e] = table[tok[bt]*E_ + e];
}

// ---------------- fp32 -> fp16 span split ----------------
__global__ void k_split(const float* __restrict__ src, __half* __restrict__ dst,
                        int total, int kshift, int nspans, int pattern) {
    int i = blockIdx.x * blockDim.x + threadIdx.x;
    if (i >= total) return;
    int kdim = 1 << kshift;
    int row = i >> kshift, k = i & (kdim - 1);
    float a = src[i];
    __half h = __float2half(a);
    __half l = __float2half(a - __half2float(h));
    size_t base = (size_t)row * ((size_t)nspans << kshift) + k;
    for (int s = 0; s < nspans; s++)
        dst[base + ((size_t)s << kshift)] = ((pattern >> s) & 1) ? l : h;
}

// ---------------- mma.sync helpers ----------------
__device__ __forceinline__ void ldsm_x4(uint32_t addr, uint32_t* r) {
    asm volatile("ldmatrix.sync.aligned.m8n8.x4.shared.b16 {%0,%1,%2,%3}, [%4];"
        : "=r"(r[0]), "=r"(r[1]), "=r"(r[2]), "=r"(r[3]) : "r"(addr));
}
__device__ __forceinline__ void mma16816(float* d, const uint32_t* a, const uint32_t* b) {
    asm volatile("mma.sync.aligned.m16n8k16.row.col.f32.f16.f16.f32 "
        "{%0,%1,%2,%3}, {%4,%5,%6,%7}, {%8,%9}, {%0,%1,%2,%3};"
        : "+f"(d[0]), "+f"(d[1]), "+f"(d[2]), "+f"(d[3])
        : "r"(a[0]), "r"(a[1]), "r"(a[2]), "r"(a[3]), "r"(b[0]), "r"(b[1]));
}
__device__ __forceinline__ void cp16(uint32_t dst, const void* src) {
    asm volatile("cp.async.cg.shared.global [%0], [%1], 16;" :: "r"(dst), "l"(src));
}
#define SWZ(r, c) ((uint32_t)((r) * 64 + (((c) ^ (((r) >> 1) & 3)) << 4)))

// ---------------- unified HMMA GEMM (3-stage, 128x256 CTA, 64x64 warp) ----------
#define HS_A 8192
#define HS_B 16384
#define HS_BOFF (3 * HS_A)
#define HS_TOTAL (3 * HS_A + 3 * HS_B)   // 73728

__global__ void __launch_bounds__(256, 1)
k_hmma(const __half* __restrict__ A, const __half* __restrict__ Bw,
       const float* __restrict__ bias, float* __restrict__ C, int K, int N) {
    extern __shared__ char hsm[];
    int tid = threadIdx.x, lane = tid & 31, warp = tid >> 5;
    int wm = warp >> 2, wn = warp & 3;
    int bm = blockIdx.y * 128, bn = blockIdx.x * 256;
    uint32_t sb = (uint32_t)__cvta_generic_to_shared(hsm);
    int nkit = K >> 5;

    float acc[4][8][4];
    #pragma unroll
    for (int i = 0; i < 4; i++)
        #pragma unroll
        for (int j = 0; j < 8; j++)
            #pragma unroll
            for (int v = 0; v < 4; v++) acc[i][j][v] = 0.f;

    auto load_stage = [&](int stage, int k0) {
        uint32_t sa = sb + stage * HS_A;
        uint32_t sbb = sb + HS_BOFF + stage * HS_B;
        #pragma unroll
        for (int i = 0; i < 2; i++) {
            int ch = tid + i * 256;
            int r = ch >> 2, c = ch & 3;
            cp16(sa + SWZ(r, c), &A[(size_t)(bm + r) * K + k0 + c * 8]);
        }
        #pragma unroll
        for (int i = 0; i < 4; i++) {
            int ch = tid + i * 256;
            int r = ch >> 2, c = ch & 3;
            cp16(sbb + SWZ(r, c), &Bw[(size_t)(bn + r) * K + k0 + c * 8]);
        }
        asm volatile("cp.async.commit_group;");
    };

    load_stage(0, 0);
    load_stage(1, 32);

    #pragma unroll 1
    for (int kt = 0; kt < nkit; kt++) {
        if (kt == nkit - 1) asm volatile("cp.async.wait_group 0;");
        else                asm volatile("cp.async.wait_group 1;");
        __syncthreads();

        if (kt + 2 < nkit) load_stage((kt + 2) % 3, (kt + 2) * 32);

        int st = kt % 3;
        uint32_t abase = sb + st * HS_A;
        uint32_t bbase = sb + HS_BOFF + st * HS_B;
        #pragma unroll
        for (int kk = 0; kk < 2; kk++) {
            int kb = kk * 2;
            uint32_t a[4][4], b[4][4];
            #pragma unroll
            for (int i = 0; i < 4; i++) {
                int r = wm * 64 + i * 16 + (lane & 15);
                int c = kb + (lane >> 4);
                ldsm_x4(abase + SWZ(r, c), a[i]);
            }
            #pragma unroll
            for (int j = 0; j < 4; j++) {
                int r = wn * 64 + j * 16 + ((lane & 16) >> 1) + (lane & 7);
                int c = kb + ((lane >> 3) & 1);
                ldsm_x4(bbase + SWZ(r, c), b[j]);
            }
            #pragma unroll
            for (int i = 0; i < 4; i++)
                #pragma unroll
                for (int jn = 0; jn < 8; jn++)
                    mma16816(acc[i][jn], a[i], b[jn >> 1] + (jn & 1) * 2);
        }
        __syncthreads();
    }

    int g = lane >> 2, q = lane & 3;
    #pragma unroll
    for (int i = 0; i < 4; i++) {
        int rr = bm + wm * 64 + i * 16 + g;
        #pragma unroll
        for (int jn = 0; jn < 8; jn++) {
            int cb = bn + wn * 64 + jn * 8 + q * 2;
            float bb0 = bias ? bias[cb] : 0.f;
            float bb1 = bias ? bias[cb + 1] : 0.f;
            C[(size_t)rr * N + cb]           = acc[i][jn][0] + bb0;
            C[(size_t)rr * N + cb + 1]       = acc[i][jn][1] + bb1;
            C[(size_t)(rr + 8) * N + cb]     = acc[i][jn][2] + bb0;
            C[(size_t)(rr + 8) * N + cb + 1] = acc[i][jn][3] + bb1;
        }
    }
}

// ---------------- persistent fused decode loop (software-pipelined, 1 gbar/step) ----
__device__ __forceinline__ void gbar_arrive_wait(unsigned target) {
    __syncthreads();
    if (threadIdx.x == 0) {
        __threadfence();
        atomicAdd(&g_bar, 1u);
        for (int i = 0; i < (1 << 22); i++) {
            if (*(volatile unsigned*)&g_bar >= target) break;
        }
        __threadfence();
    }
    __syncthreads();
}

__global__ void __launch_bounds__(256, 2)
k_loop(const float* __restrict__ W_hh, const float* __restrict__ enc,
       const int* __restrict__ lens) {
    __shared__ float w_sh[8][H_];
    __shared__ float apart[8][8][33];
    __shared__ float sg[8][33];
    __shared__ float hb_sh[H_];
    __shared__ float sc_sh[S_];
    __shared__ float red[34];
    __shared__ float cpart[4][64];
    int tid = threadIdx.x;
    int bid = blockIdx.x;
    int ub  = bid * 2;
    int warp = tid >> 5, lane = tid & 31;

    for (int rr = 0; rr < 8; rr++) {
        int row = (rr & 3) * H_ + ub + (rr >> 2);
        for (int k = tid; k < H_; k += 256)
            w_sh[rr][k] = W_hh[(size_t)row * H_ + k];
    }
    __syncthreads();

    int b2 = bid >> 3, j = bid & 7;
    int len = lens[b2];
    unsigned nb = 0;

    // phase t: A(t) computes h(t+1); BC(t-1) consumes h(t) + proj/enc.
    for (int t = 0; t <= T_; t++) {
        // ---- Phase A for step t ----
        if (t < T_) {
            const float* h_in  = g_h[t & 1];
            float*       h_out = g_h[(t + 1) & 1];
            float acc[8];
            #pragma unroll
            for (int r = 0; r < 8; r++) acc[r] = 0.f;
            const float4* hp = (const float4*)(h_in + lane * H_ + warp * 64);
            #pragma unroll
            for (int k4 = 0; k4 < 16; k4++) {
                float4 hv = hp[k4];
                #pragma unroll
                for (int r = 0; r < 8; r++) {
                    float4 wv = *(const float4*)&w_sh[r][warp * 64 + k4 * 4];
                    acc[r] += hv.x*wv.x + hv.y*wv.y + hv.z*wv.z + hv.w*wv.w;
                }
            }
            #pragma unroll
            for (int r = 0; r < 8; r++) apart[warp][r][lane] = acc[r];
            __syncthreads();
            {
                float gv = 0.f;
                #pragma unroll
                for (int s = 0; s < 8; s++) gv += apart[s][warp][lane];
                int row = (warp & 3) * H_ + ub + (warp >> 2);
                gv += g_X[(size_t)(lane * T_ + t) * G4_ + row];
                sg[warp][lane] = gv;
            }
            __syncthreads();
            if (tid < 64) {
                int q2 = tid >> 5, b3 = tid & 31;
                int u  = ub + q2;
                float iv = sg[q2*4 + 0][b3];
                float fv = sg[q2*4 + 1][b3];
                float gg = sg[q2*4 + 2][b3];
                float ov = sg[q2*4 + 3][b3];
                float si = 1.f / (1.f + expf(-iv));
                float sf = 1.f / (1.f + expf(-fv));
                float so = 1.f / (1.f + expf(-ov));
                float c_old = g_c[b3 * H_ + u];
                float c_new = sf * c_old + si * tanhf(gg);
                g_c[b3 * H_ + u]   = c_new;
                h_out[b3 * H_ + u] = so * tanhf(c_new);
            }
            __syncthreads();
        }

        // ---- Phase B+C for step t-1 (uses h(t) = g_h[t&1]) ----
        if (t > 0) {
            int ts = t - 1;
            const float* hn = g_h[t & 1] + b2 * H_;
            for (int i = tid; i < H_; i += 256) hb_sh[i] = hn[i];
            __syncthreads();
            // B: scores s in [j*16, j*16+16)
            {
                int s0 = j * 16 + warp * 2;
                const float* p0 = g_proj + ((size_t)b2 * S_ + s0) * H_;
                const float* p1 = p0 + H_;
                float a0 = 0.f, a1 = 0.f;
                #pragma unroll 4
                for (int k = lane; k < H_; k += 32) {
                    float hv = hb_sh[k];
                    a0 += hv * p0[k];
                    a1 += hv * p1[k];
                }
                #pragma unroll
                for (int o = 16; o; o >>= 1) {
                    a0 += __shfl_xor_sync(0xFFFFFFFFu, a0, o);
                    a1 += __shfl_xor_sync(0xFFFFFFFFu, a1, o);
                }
                if (lane == 0) { g_sc[b2 * S_ + s0] = a0; g_sc[b2 * S_ + s0 + 1] = a1; }
            }
            __syncthreads();
            // per-batch sub-barrier: wait for the 8 sibling blocks of b2
            if (tid == 0) {
                __threadfence();
                atomicAdd(&g_cnt[b2 * 32], 1u);
                unsigned tgt = 8u * (unsigned)t;
                for (int i = 0; i < (1 << 22); i++) {
                    if (*(volatile unsigned*)&g_cnt[b2 * 32] >= tgt) break;
                }
                __threadfence();
            }
            __syncthreads();
            // C: softmax + ctx chunk
            {
                if (tid < S_) {
                    float v = g_sc[b2 * S_ + tid];
                    sc_sh[tid] = (tid < len) ? v : -1e9f;
                }
                __syncthreads();
                float m = (tid < S_) ? sc_sh[tid] : -1e30f;
                #pragma unroll
                for (int o = 16; o; o >>= 1) m = fmaxf(m, __shfl_xor_sync(0xFFFFFFFFu, m, o));
                if (lane == 0) red[warp] = m;
                __syncthreads();
                if (tid == 0) {
                    float mm = red[0];
                    for (int i = 1; i < 8; i++) mm = fmaxf(mm, red[i]);
                    red[32] = mm;
                }
                __syncthreads();
                float mx = red[32];
                float p = (tid < S_) ? expf(sc_sh[tid] - mx) : 0.f;
                float ps = p;
                #pragma unroll
                for (int o = 16; o; o >>= 1) ps += __shfl_xor_sync(0xFFFFFFFFu, ps, o);
                if (lane == 0) red[warp] = ps;
                __syncthreads();
                if (tid == 0) {
                    float sm = 0.f;
                    for (int i = 0; i < 8; i++) sm += red[i];
                    red[33] = 1.f / sm;
                }
                __syncthreads();
                if (tid < S_) sc_sh[tid] = p * red[33];
                __syncthreads();

                int cc = tid & 63, pq = tid >> 6;
                int e  = j * 64 + cc;
                const float* eb = enc + ((size_t)b2 * S_ + pq * 32) * ENC_ + e;
                float a = 0.f;
                #pragma unroll 8
                for (int s = 0; s < 32; s++) a += sc_sh[pq * 32 + s] * eb[(size_t)s * ENC_];
                cpart[pq][cc] = a;
                __syncthreads();
                if (tid < 64) {
                    float cx = cpart[0][tid] + cpart[1][tid] + cpart[2][tid] + cpart[3][tid];
                    float* dst = g_hcat + (size_t)(b2 * T_ + ts) * (H_ + ENC_);
                    dst[H_ + j * 64 + tid] = cx;
                    dst[j * 64 + tid] = g_h[t & 1][b2 * H_ + j * 64 + tid];
                }
                __syncthreads();
            }
        }

        // ---- one global barrier per phase (none after the final BC-only phase) ----
        if (t < T_) { nb++; gbar_arrive_wait(nb * 256); }
    }
}

// ---------------- launch ----------------
extern "C" void kernel_launch(void* const* d_in, const int* in_sizes, int n_in,
                              void* d_out, int out_size) {
    const int*   gold   = (const int*)  d_in[0];
    const float* enc    = (const float*)d_in[1];
    const int*   lens   = (const int*)  d_in[2];
    const float* h0     = (const float*)d_in[3];
    const float* c0     = (const float*)d_in[4];
    const float* table  = (const float*)d_in[5];
    const float* W_ih   = (const float*)d_in[6];
    const float* W_hh   = (const float*)d_in[7];
    const float* b_ih   = (const float*)d_in[8];
    const float* b_hh   = (const float*)d_in[9];
    const float* Wa     = (const float*)d_in[10];
    const float* Wc_w   = (const float*)d_in[11];
    const float* Wc_b   = (const float*)d_in[12];
    const float* Wo_w   = (const float*)d_in[13];
    const float* Wo_b   = (const float*)d_in[14];
    float* out = (float*)d_out;

    float *p_emb, *p_X, *p_proj, *p_hcat, *p_ho, *p_bias;
    cudaGetSymbolAddress((void**)&p_emb,  g_emb);
    cudaGetSymbolAddress((void**)&p_X,    g_X);
    cudaGetSymbolAddress((void**)&p_proj, g_proj);
    cudaGetSymbolAddress((void**)&p_hcat, g_hcat);
    cudaGetSymbolAddress((void**)&p_ho,   g_ho);
    cudaGetSymbolAddress((void**)&p_bias, g_bias);
    __half *pX_A, *pX_B, *pP_A, *pP_B, *pW_A, *pW_B, *pL_A, *pL_B;
    cudaGetSymbolAddress((void**)&pX_A, gX_A);
    cudaGetSymbolAddress((void**)&pX_B, gX_B);
    cudaGetSymbolAddress((void**)&pP_A, gP_A);
    cudaGetSymbolAddress((void**)&pP_B, gP_B);
    cudaGetSymbolAddress((void**)&pW_A, gW_A);
    cudaGetSymbolAddress((void**)&pW_B, gW_B);
    cudaGetSymbolAddress((void**)&pL_A, gL_A);
    cudaGetSymbolAddress((void**)&pL_B, gL_B);

    cudaFuncSetAttribute(k_hmma, cudaFuncAttributeMaxDynamicSharedMemorySize, HS_TOTAL);

    k_init<<<64, 256>>>(h0, c0, b_ih, b_hh);
    k_embed<<<BT_, 256>>>(gold, table);

    // input splits (independent of the loop)
    k_split<<<(G4_*E_ + 255)/256, 256>>>(W_ih, pX_B, G4_*E_, 8, 3, 0b010);
    k_split<<<(B_*S_*ENC_ + 255)/256, 256>>>(enc, pP_A, B_*S_*ENC_, 9, 3, 0b100);
    k_split<<<(H_*ENC_ + 255)/256, 256>>>(Wa, pP_B, H_*ENC_, 9, 3, 0b010);
    k_split<<<(V_*H_ + 255)/256, 256>>>(Wo_w, pL_B, V_*H_, 9, 1, 0);
    k_split<<<(H_*(H_+ENC_) + 255)/256, 256>>>(Wc_w, pW_B, H_*(H_+ENC_), 10, 2, 0b10);
    k_split<<<(BT_*E_ + 255)/256, 256>>>(p_emb, pX_A, BT_*E_, 8, 3, 0b100);

    // X = emb @ W_ih^T + bias   (3-span fp16, K=768)
    k_hmma<<<dim3(G4_/256, BT_/128), 256, HS_TOTAL>>>(pX_A, pX_B, p_bias, p_X, 3*E_, G4_);
    // proj = enc @ Wa^T         (3-span fp16, K=1536)
    k_hmma<<<dim3(H_/256, (B_*S_)/128), 256, HS_TOTAL>>>(pP_A, pP_B, nullptr, p_proj, 3*ENC_, H_);

    // fused persistent decode loop (software-pipelined, 64 global barriers)
    k_loop<<<256, 256>>>(W_hh, enc, lens);

    // HO = [h;ctx] @ Wc_w^T + Wc_b  (2-span fp16, K=2048)
    k_split<<<(BT_*(H_+ENC_) + 255)/256, 256>>>(p_hcat, pW_A, BT_*(H_+ENC_), 10, 2, 0b00);
    k_hmma<<<dim3(H_/256, BT_/128), 256, HS_TOTAL>>>(pW_A, pW_B, Wc_b, p_ho, 2*(H_+ENC_), H_);

    // logits = ho @ Wo^T + Wo_b  (single-span fp16, K=512)
    k_split<<<(BT_*H_ + 255)/256, 256>>>(p_ho, pL_A, BT_*H_, 9, 1, 0);
    k_hmma<<<dim3(V_/256, BT_/128), 256, HS_TOTAL>>>(pL_A, pL_B, Wo_b, out, H_, V_);
}